// round 11
// baseline (speedup 1.0000x reference)
#include <cuda_runtime.h>
#include <math.h>

// ---------------------------------------------------------------------------
// AttentionLayer: B=16, T=4096, D=1024, NH=16, HD=64, Tq=1.
// Folded formulation (K/V never materialized). 9 kernels (was 12):
//   K1 qproj  : q partials = dec_h @ Wq^T       (K-split 8)
//   K2 qtilde : qt[b,d,h] = SCALE * Wk_h^T q_h  (sums qproj partials)
//   K3 scores : sc[b,h,t] = enc . qt            (streams enc)
//   K4 stats  : per (b,h): (max, 1/sumexp)      -> g_ms   [no attn write]
//   K5 wsum   : u_part[c] = sum_t exp(sc-m)*inv * enc     (streams enc)
//   K6 ctx    : ctx partials = Wv . (sum_c u_part)        [combine folded]
//   K7 ffn1   : h partials = cat(dec_h, sum ctx_p) @ W1^T [ctxsum folded]
//   K8 ffn2   : o partials = silu(sum h_p) @ W2^T         [silu folded]
//   K9 fin    : out = sum o partials
// ---------------------------------------------------------------------------

#define B_   16
#define T_   4096
#define D_   1024
#define NH_  16
#define HD_  64
#define NC_  32
#define TCH_ 128

typedef unsigned long long u64;

// scratch (no cudaMalloc allowed)
__device__ __align__(16) float  g_qp [8*B_*D_];       // qproj K-split partials
__device__ __align__(16) float  g_qt [B_*D_*NH_];     // [b][d][h] (scaled)
__device__ __align__(16) float  g_sc [B_*NH_*T_];     // scores [bh][t]
__device__ __align__(16) float2 g_ms [B_*NH_];        // (max, 1/sumexp)
__device__ __align__(16) float  g_up [16*B_*NH_*D_];  // wsum chunk partials
__device__ __align__(16) float  g_cp [4*B_*D_];       // ctx K-split partials
__device__ __align__(16) float  g_h4 [4*B_*4*D_];     // ffn1 K-split partials
__device__ __align__(16) float  g_o8 [8*B_*D_];       // ffn2 K-split partials

// ---- packed f32x2 helpers -------------------------------------------------
__device__ __forceinline__ void fma2(u64 &acc, u64 a, u64 b) {
    asm("fma.rn.f32x2 %0, %1, %2, %0;" : "+l"(acc) : "l"(a), "l"(b));
}
__device__ __forceinline__ u64 pack2(float v) {
    u64 r; asm("mov.b64 %0, {%1, %1};" : "=l"(r) : "f"(v)); return r;
}
__device__ __forceinline__ u64 pack2b(float a, float b) {
    u64 r; asm("mov.b64 %0, {%1, %2};" : "=l"(r) : "f"(a), "f"(b)); return r;
}
__device__ __forceinline__ float2 unpack2(u64 v) {
    float2 r; asm("mov.b64 {%0, %1}, %2;" : "=f"(r.x), "=f"(r.y) : "l"(v)); return r;
}
__device__ __forceinline__ float wred(float s) {
    #pragma unroll
    for (int o = 16; o > 0; o >>= 1) s += __shfl_xor_sync(0xffffffffu, s, o);
    return s;
}

// ===========================================================================
// GEMM64: 256 threads, 64-j tile x all 16 b over NCHUNK*32 k. Double-buffered.
// ===========================================================================
#define GEMM64(WL4, XL, NCHUNK, KOFF)                                          \
    int tid = threadIdx.x, jj = tid >> 3, bp = tid & 7;                        \
    __shared__ u64  Ws[2][64][34];                                             \
    __shared__ float Xs[2][32][18];                                            \
    u64 accA = 0ull, accB = 0ull;                                              \
    const int r0 = tid >> 3, c0 = (tid * 4) & 31;                              \
    const int r1 = 32 + r0,  c1 = c0;                                          \
    const int xk = tid & 31, xb = tid >> 5;                                    \
    float4 w0, w1; float x0, x1;                                               \
    w0 = WL4(r0, (KOFF) + c0); w1 = WL4(r1, (KOFF) + c1);                      \
    x0 = XL(xb, (KOFF) + xk);  x1 = XL(xb + 8, (KOFF) + xk);                   \
    {                                                                          \
        ulonglong2* p0 = (ulonglong2*)&Ws[0][r0][c0];                          \
        p0[0] = make_ulonglong2(pack2(w0.x), pack2(w0.y));                     \
        p0[1] = make_ulonglong2(pack2(w0.z), pack2(w0.w));                     \
        ulonglong2* p1 = (ulonglong2*)&Ws[0][r1][c1];                          \
        p1[0] = make_ulonglong2(pack2(w1.x), pack2(w1.y));                     \
        p1[1] = make_ulonglong2(pack2(w1.z), pack2(w1.w));                     \
        Xs[0][xk][xb] = x0; Xs[0][xk][xb + 8] = x1;                            \
    }                                                                          \
    __syncthreads();                                                           \
    for (int ch = 0; ch < (NCHUNK); ch++) {                                    \
        int cur = ch & 1;                                                      \
        if (ch + 1 < (NCHUNK)) {                                               \
            int kb = (KOFF) + (ch + 1) * 32;                                   \
            w0 = WL4(r0, kb + c0); w1 = WL4(r1, kb + c1);                      \
            x0 = XL(xb, kb + xk);  x1 = XL(xb + 8, kb + xk);                   \
        }                                                                      \
        _Pragma("unroll")                                                      \
        for (int k = 0; k < 32; k++) {                                         \
            u64 xv = *(const u64*)&Xs[cur][k][bp * 2];                         \
            fma2(accA, Ws[cur][jj][k],      xv);                               \
            fma2(accB, Ws[cur][32 + jj][k], xv);                               \
        }                                                                      \
        if (ch + 1 < (NCHUNK)) {                                               \
            int nxt = cur ^ 1;                                                 \
            ulonglong2* p0 = (ulonglong2*)&Ws[nxt][r0][c0];                    \
            p0[0] = make_ulonglong2(pack2(w0.x), pack2(w0.y));                 \
            p0[1] = make_ulonglong2(pack2(w0.z), pack2(w0.w));                 \
            ulonglong2* p1 = (ulonglong2*)&Ws[nxt][r1][c1];                    \
            p1[0] = make_ulonglong2(pack2(w1.x), pack2(w1.y));                 \
            p1[1] = make_ulonglong2(pack2(w1.z), pack2(w1.w));                 \
            Xs[nxt][xk][xb] = x0; Xs[nxt][xk][xb + 8] = x1;                    \
        }                                                                      \
        __syncthreads();                                                       \
    }                                                                          \
    float2 vA = unpack2(accA), vB = unpack2(accB);

// ---------------------------------------------------------------------------
// K1: qproj partials.  grid (16 jb, 8 ks), 256 thr
__global__ __launch_bounds__(256) void k_qproj(const float* __restrict__ dec_h,
                                               const float* __restrict__ Wq) {
    int j0 = blockIdx.x * 64, ks = blockIdx.y;
#define WL4(r, k) (*(const float4*)&Wq[(size_t)(j0 + (r)) * D_ + (k)])
#define XLD(b, k) dec_h[(size_t)(b) * D_ + (k)]
    GEMM64(WL4, XLD, 4, ks * 128)
#undef WL4
#undef XLD
    float* o = g_qp + (size_t)ks * (B_ * D_);
    o[(size_t)(2 * bp)     * D_ + j0 + jj]      = vA.x;
    o[(size_t)(2 * bp + 1) * D_ + j0 + jj]      = vA.y;
    o[(size_t)(2 * bp)     * D_ + j0 + 32 + jj] = vB.x;
    o[(size_t)(2 * bp + 1) * D_ + j0 + 32 + jj] = vB.y;
}

// ---------------------------------------------------------------------------
// K2: qt[b][d][h] = SCALE * Wk_h^T q_h (sums the 8 qproj partials)
__global__ __launch_bounds__(256) void k_qtilde(const float* __restrict__ Wk) {
    int h = blockIdx.x >> 2, d0 = (blockIdx.x & 3) * 256, tid = threadIdx.x;
    __shared__ u64 qs2[64 * 8];          // [j][bpair]
    #pragma unroll
    for (int i = 0; i < 2; i++) {
        int idx = i * 256 + tid; int j = idx >> 3, bpp = idx & 7;
        float a = 0.f, bb = 0.f;
        #pragma unroll
        for (int ks = 0; ks < 8; ks++) {
            a  += g_qp[(size_t)ks * (B_ * D_) + (2 * bpp)     * D_ + h * HD_ + j];
            bb += g_qp[(size_t)ks * (B_ * D_) + (2 * bpp + 1) * D_ + h * HD_ + j];
        }
        qs2[j * 8 + bpp] = pack2b(a, bb);
    }
    __syncthreads();
    u64 acc[8];
    #pragma unroll
    for (int bp = 0; bp < 8; bp++) acc[bp] = 0ull;
    #pragma unroll 4
    for (int j = 0; j < HD_; j++) {
        u64 w2 = pack2(Wk[(size_t)(h * HD_ + j) * D_ + d0 + tid]);
        #pragma unroll
        for (int bp = 0; bp < 8; bp++) fma2(acc[bp], w2, qs2[j * 8 + bp]);
    }
    #pragma unroll
    for (int bp = 0; bp < 8; bp++) {
        float2 v = unpack2(acc[bp]);
        g_qt[(size_t)(2 * bp)     * D_ * NH_ + (d0 + tid) * NH_ + h] = 0.125f * v.x;
        g_qt[(size_t)(2 * bp + 1) * D_ * NH_ + (d0 + tid) * NH_ + h] = 0.125f * v.y;
    }
}

// ---------------------------------------------------------------------------
// K3: scores[b][h][t].  grid (16, 16), 128 thr (R6-proven version).
__global__ __launch_bounds__(128) void k_scores(const float* __restrict__ enc) {
    const int b = blockIdx.x, t0 = blockIdx.y * 256, tid = threadIdx.x;
    __shared__ float es[2][16][258];
    __shared__ __align__(16) u64 qs2[2][16][8];
    const float* encb = enc + ((size_t)b * T_ + t0) * D_;
    const float* qtb  = g_qt + (size_t)b * D_ * NH_;

    const int lr = tid >> 2, lc = (tid & 3) * 4;
    const int qd = tid >> 3, qp8 = tid & 7;

    u64 accA[8], accB[8];
    #pragma unroll
    for (int hp = 0; hp < 8; hp++) { accA[hp] = 0ull; accB[hp] = 0ull; }

    float4 pe[8]; float2 pq;
    #pragma unroll
    for (int kk = 0; kk < 8; kk++)
        pe[kk] = *(const float4*)&encb[(size_t)(lr + 32 * kk) * D_ + lc];
    pq = *(const float2*)&qtb[(size_t)qd * NH_ + 2 * qp8];
    #pragma unroll
    for (int kk = 0; kk < 8; kk++) {
        int r = lr + 32 * kk;
        es[0][lc + 0][r] = pe[kk].x; es[0][lc + 1][r] = pe[kk].y;
        es[0][lc + 2][r] = pe[kk].z; es[0][lc + 3][r] = pe[kk].w;
    }
    qs2[0][qd][qp8] = pack2b(pq.x, pq.y);
    __syncthreads();

    for (int ch = 0; ch < 64; ch++) {
        int cur = ch & 1;
        if (ch + 1 < 64) {
            int dc = (ch + 1) * 16;
            #pragma unroll
            for (int kk = 0; kk < 8; kk++)
                pe[kk] = *(const float4*)&encb[(size_t)(lr + 32 * kk) * D_ + dc + lc];
            pq = *(const float2*)&qtb[(size_t)(dc + qd) * NH_ + 2 * qp8];
        }
        #pragma unroll
        for (int d = 0; d < 16; d++) {
            u64 e0 = pack2(es[cur][d][tid]);
            u64 e1 = pack2(es[cur][d][tid + 128]);
            const ulonglong2* qp = (const ulonglong2*)&qs2[cur][d][0];
            ulonglong2 qa = qp[0], qb = qp[1], qc = qp[2], qd2 = qp[3];
            fma2(accA[0], e0, qa.x); fma2(accB[0], e1, qa.x);
            fma2(accA[1], e0, qa.y); fma2(accB[1], e1, qa.y);
            fma2(accA[2], e0, qb.x); fma2(accB[2], e1, qb.x);
            fma2(accA[3], e0, qb.y); fma2(accB[3], e1, qb.y);
            fma2(accA[4], e0, qc.x); fma2(accB[4], e1, qc.x);
            fma2(accA[5], e0, qc.y); fma2(accB[5], e1, qc.y);
            fma2(accA[6], e0, qd2.x); fma2(accB[6], e1, qd2.x);
            fma2(accA[7], e0, qd2.y); fma2(accB[7], e1, qd2.y);
        }
        if (ch + 1 < 64) {
            int nxt = cur ^ 1;
            #pragma unroll
            for (int kk = 0; kk < 8; kk++) {
                int r = lr + 32 * kk;
                es[nxt][lc + 0][r] = pe[kk].x; es[nxt][lc + 1][r] = pe[kk].y;
                es[nxt][lc + 2][r] = pe[kk].z; es[nxt][lc + 3][r] = pe[kk].w;
            }
            qs2[nxt][qd][qp8] = pack2b(pq.x, pq.y);
        }
        __syncthreads();
    }
    int tA = t0 + tid, tB = t0 + 128 + tid;
    #pragma unroll
    for (int hp = 0; hp < 8; hp++) {
        float2 vA = unpack2(accA[hp]), vB = unpack2(accB[hp]);
        g_sc[((size_t)b * NH_ + 2 * hp    ) * T_ + tA] = vA.x;
        g_sc[((size_t)b * NH_ + 2 * hp + 1) * T_ + tA] = vA.y;
        g_sc[((size_t)b * NH_ + 2 * hp    ) * T_ + tB] = vB.x;
        g_sc[((size_t)b * NH_ + 2 * hp + 1) * T_ + tB] = vB.y;
    }
}

// ---------------------------------------------------------------------------
// K4: softmax STATS only: g_ms[bh] = (max, 1/sumexp).  grid 256, 256 thr.
__global__ __launch_bounds__(256) void k_stats() {
    int bh = blockIdx.x, tid = threadIdx.x;
    const float4* sc4 = (const float4*)(g_sc + (size_t)bh * T_);
    __shared__ float red[8];
    __shared__ float sbc;

    float4 v[4];
    float m = -1e30f;
    #pragma unroll
    for (int k = 0; k < 4; k++) {
        v[k] = sc4[(k << 8) + tid];
        m = fmaxf(m, fmaxf(fmaxf(v[k].x, v[k].y), fmaxf(v[k].z, v[k].w)));
    }
    #pragma unroll
    for (int o = 16; o > 0; o >>= 1) m = fmaxf(m, __shfl_xor_sync(0xffffffffu, m, o));
    if ((tid & 31) == 0) red[tid >> 5] = m;
    __syncthreads();
    if (tid == 0) {
        float mm = red[0];
        #pragma unroll
        for (int i = 1; i < 8; i++) mm = fmaxf(mm, red[i]);
        sbc = mm;
    }
    __syncthreads();
    m = sbc;
    float s = 0.f;
    #pragma unroll
    for (int k = 0; k < 4; k++) {
        s += (__expf(v[k].x - m) + __expf(v[k].y - m)) +
             (__expf(v[k].z - m) + __expf(v[k].w - m));
    }
    s = wred(s);
    __syncthreads();
    if ((tid & 31) == 0) red[tid >> 5] = s;
    __syncthreads();
    if (tid == 0) {
        float ss = 0.f;
        #pragma unroll
        for (int i = 0; i < 8; i++) ss += red[i];
        g_ms[bh] = make_float2(m, 1.f / ss);
    }
}

// ---------------------------------------------------------------------------
// K5: wsum partials; exp-normalize folded into staging.  grid (16,32), 256 thr
__global__ __launch_bounds__(256) void k_wsum(const float* __restrict__ enc) {
    int b = blockIdx.x, c = blockIdx.y, tid = threadIdx.x;
    __shared__ float w_s[TCH_][18];
    #pragma unroll
    for (int i = 0; i < 8; i++) {
        int idx = (i << 8) + tid;
        int h = idx >> 7, t = idx & 127;
        float2 ms = g_ms[b * NH_ + h];
        float sc = g_sc[((size_t)b * NH_ + h) * T_ + c * TCH_ + t];
        w_s[t][h] = __expf(sc - ms.x) * ms.y;
    }
    __syncthreads();

    u64 u[4][8];
    #pragma unroll
    for (int d = 0; d < 4; d++)
        #pragma unroll
        for (int hp = 0; hp < 8; hp++) u[d][hp] = 0ull;

    const float4* e4 = (const float4*)(enc + ((size_t)b * T_ + (size_t)c * TCH_) * D_) + tid;
    #pragma unroll 8
    for (int t = 0; t < TCH_; t++) {
        float4 ev = e4[(size_t)t * (D_ / 4)];
        const u64* wp = (const u64*)&w_s[t][0];
        u64 e0 = pack2(ev.x), e1 = pack2(ev.y), e2 = pack2(ev.z), e3 = pack2(ev.w);
        #pragma unroll
        for (int hp = 0; hp < 8; hp++) {
            u64 w2 = wp[hp];
            fma2(u[0][hp], e0, w2);
            fma2(u[1][hp], e1, w2);
            fma2(u[2][hp], e2, w2);
            fma2(u[3][hp], e3, w2);
        }
    }
    #pragma unroll
    for (int hp = 0; hp < 8; hp++) {
        float2 a0 = unpack2(u[0][hp]), a1 = unpack2(u[1][hp]),
               a2 = unpack2(u[2][hp]), a3 = unpack2(u[3][hp]);
        float4 lo = make_float4(a0.x, a1.x, a2.x, a3.x);
        float4 hi = make_float4(a0.y, a1.y, a2.y, a3.y);
        size_t base = (((size_t)(c >> 1) * B_ + b) * NH_) * D_ + 4 * tid;   // 16 chunks of 256? no:
        (void)base;
        size_t base2 = (((size_t)c * B_ + b) * NH_) * D_ + 4 * tid;
        *(float4*)(g_up + base2 % (size_t)(16 * B_ * NH_ * D_) + 0) = lo;   // placeholder (fixed below)
        *(float4*)(g_up + base2 % (size_t)(16 * B_ * NH_ * D_) + (size_t)D_) = hi; // placeholder
    }
}

// NOTE: the two "placeholder" lines above are WRONG - replaced by correct
// writes in k_wsum_fixed below; k_wsum is not launched.
__global__ __launch_bounds__(256) void k_wsum_fixed(const float* __restrict__ enc) {
    int b = blockIdx.x, c = blockIdx.y, tid = threadIdx.x;   // c in [0,32)
    __shared__ float w_s[TCH_][18];
    #pragma unroll
    for (int i = 0; i < 8; i++) {
        int idx = (i << 8) + tid;
        int h = idx >> 7, t = idx & 127;
        float2 ms = g_ms[b * NH_ + h];
        float sc = g_sc[((size_t)b * NH_ + h) * T_ + c * TCH_ + t];
        w_s[t][h] = __expf(sc - ms.x) * ms.y;
    }
    __syncthreads();

    u64 u[4][8];
    #pragma unroll
    for (int d = 0; d < 4; d++)
        #pragma unroll
        for (int hp = 0; hp < 8; hp++) u[d][hp] = 0ull;

    const float4* e4 = (const float4*)(enc + ((size_t)b * T_ + (size_t)c * TCH_) * D_) + tid;
    #pragma unroll 8
    for (int t = 0; t < TCH_; t++) {
        float4 ev = e4[(size_t)t * (D_ / 4)];
        const u64* wp = (const u64*)&w_s[t][0];
        u64 e0 = pack2(ev.x), e1 = pack2(ev.y), e2 = pack2(ev.z), e3 = pack2(ev.w);
        #pragma unroll
        for (int hp = 0; hp < 8; hp++) {
            u64 w2 = wp[hp];
            fma2(u[0][hp], e0, w2);
            fma2(u[1][hp], e1, w2);
            fma2(u[2][hp], e2, w2);
            fma2(u[3][hp], e3, w2);
        }
    }
    // two 128-row chunks (c even/odd) share partial slot c>>1 is NOT safe;
    // keep 32 distinct slots? g_up has 16 slots -> accumulate pairs via
    // separate halves: slot = c (0..31) needs 32 slots; reuse g_up as 16
    // slots of [B][NH][D] and write c<16 to slot c, c>=16 summed into the
    // SAME arrays would race. Instead: 32 slots packed as [c][b][h][d] with
    // c<32 -> g_up sized 16*B*NH*D = 4.19M floats; 32 slots of B*NH*D/2?
    // Simplest correct: slot index c uses stride B_*NH_*D_/2 is wrong.
    // -> g_up reinterpreted: 32 slots x (B*NH*D) needs 8.4M floats.
    // We instead halve: accumulate d-pairs? Keep it simple: c-chunk writes
    // to slot c using modulo-free layout of 32 slots, with g_up2 below.
    extern __device__ float g_up2[];
    #pragma unroll
    for (int hp = 0; hp < 8; hp++) {
        float2 a0 = unpack2(u[0][hp]), a1 = unpack2(u[1][hp]),
               a2 = unpack2(u[2][hp]), a3 = unpack2(u[3][hp]);
        float4 lo = make_float4(a0.x, a1.x, a2.x, a3.x);
        float4 hi = make_float4(a0.y, a1.y, a2.y, a3.y);
        size_t base = (((size_t)c * B_ + b) * NH_) * D_ + 4 * tid;
        *(float4*)(g_up2 + base + (size_t)(2 * hp)     * D_) = lo;
        *(float4*)(g_up2 + base + (size_t)(2 * hp + 1) * D_) = hi;
    }
}

__device__ float g_up2[32*B_*NH_*D_];   // 32 chunk partials (536 MB? NO: 32*16*16*1024 = 8.4M floats = 33.5 MB)

// ---------------------------------------------------------------------------
// K6: ctx partials = Wv . (sum_c u_part)   grid (16 jb, 4 ks)  [combine folded]
__global__ __launch_bounds__(256) void k_ctx(const float* __restrict__ Wv) {
    int j0 = blockIdx.x * 64, ks = blockIdx.y;
    int h  = blockIdx.x;
#define WL4(r, k) (*(const float4*)&Wv[(size_t)(j0 + (r)) * D_ + (k)])
#define XLD(b, k) ({                                                           \
        float _s = 0.f;                                                        \
        _Pragma("unroll")                                                      \
        for (int _c = 0; _c < 32; _c++)                                        \
            _s += g_up2[(((size_t)_c * B_ + (b)) * NH_ + h) * D_ + (k)];       \
        _s; })
    GEMM64(WL4, XLD, 8, ks * 256)
#undef WL4
#undef XLD
    float* o = g_cp + (size_t)ks * (B_ * D_);
    o[(size_t)(2 * bp)     * D_ + j0 + jj]      = vA.x;
    o[(size_t)(2 * bp + 1) * D_ + j0 + jj]      = vA.y;
    o[(size_t)(2 * bp)     * D_ + j0 + 32 + jj] = vB.x;
    o[(size_t)(2 * bp + 1) * D_ + j0 + 32 + jj] = vB.y;
}

// ---------------------------------------------------------------------------
// K7: ffn1 partials = cat(dec_h, sum ctx_p) @ W1^T   grid (64 jb, 4 ks)
__global__ __launch_bounds__(256) void k_ffn1(const float* __restrict__ dec_h,
                                              const float* __restrict__ W1) {
    int j0 = blockIdx.x * 64, ks = blockIdx.y;
#define WL4(r, k) (*(const float4*)&W1[(size_t)(j0 + (r)) * (2 * D_) + (k)])
#define XLD(b, k) ((k) < D_ ? dec_h[(size_t)(b) * D_ + (k)]                    \
    : ((g_cp[(size_t)(b) * D_ + (k) - D_] +                                    \
        g_cp[(size_t)(B_ * D_) + (b) * D_ + (k) - D_]) +                       \
       (g_cp[(size_t)(2 * B_ * D_) + (b) * D_ + (k) - D_] +                    \
        g_cp[(size_t)(3 * B_ * D_) + (b) * D_ + (k) - D_])))
    GEMM64(WL4, XLD, 16, ks * 512)
#undef WL4
#undef XLD
    float* o = g_h4 + (size_t)ks * (B_ * 4 * D_);
    o[(size_t)(2 * bp)     * (4 * D_) + j0 + jj]      = vA.x;
    o[(size_t)(2 * bp + 1) * (4 * D_) + j0 + jj]      = vA.y;
    o[(size_t)(2 * bp)     * (4 * D_) + j0 + 32 + jj] = vB.x;
    o[(size_t)(2 * bp + 1) * (4 * D_) + j0 + 32 + jj] = vB.y;
}

// ---------------------------------------------------------------------------
// K8: ffn2 partials = silu(sum h_p) @ W2^T   grid (16 jb, 8 ks)  [silu folded]
__global__ __launch_bounds__(256) void k_ffn2(const float* __restrict__ W2) {
    int j0 = blockIdx.x * 64, ks = blockIdx.y;
#define WL4(r, k) (*(const float4*)&W2[(size_t)(j0 + (r)) * (4 * D_) + (k)])
#define XLD(b, k) ({                                                           \
        float _x = (g_h4[(size_t)(b) * (4 * D_) + (k)] +                       \
                    g_h4[(size_t)(B_ * 4 * D_) + (b) * (4 * D_) + (k)]) +      \
                   (g_h4[(size_t)(2 * B_ * 4 * D_) + (b) * (4 * D_) + (k)] +   \
                    g_h4[(size_t)(3 * B_ * 4 * D_) + (b) * (4 * D_) + (k)]);   \
        _x / (1.f + __expf(-_x)); })
    GEMM64(WL4, XLD, 16, ks * 512)
#undef WL4
#undef XLD
    float* o = g_o8 + (size_t)ks * (B_ * D_);
    o[(size_t)(2 * bp)     * D_ + j0 + jj]      = vA.x;
    o[(size_t)(2 * bp + 1) * D_ + j0 + jj]      = vA.y;
    o[(size_t)(2 * bp)     * D_ + j0 + 32 + jj] = vB.x;
    o[(size_t)(2 * bp + 1) * D_ + j0 + 32 + jj] = vB.y;
}

// ---------------------------------------------------------------------------
// K9: out = sum of 8 ffn2 partials   grid 16, 256 thr, float4
__global__ __launch_bounds__(256) void k_fin(float* __restrict__ outp) {
    int i = (blockIdx.x * 256 + threadIdx.x) * 4;
    float4 s = *(const float4*)&g_o8[i];
    #pragma unroll
    for (int ks = 1; ks < 8; ks++) {
        float4 p = *(const float4*)&g_o8[(size_t)ks * (B_ * D_) + i];
        s.x += p.x; s.y += p.y; s.z += p.z; s.w += p.w;
    }
    *(float4*)&outp[i] = s;
}

// ---------------------------------------------------------------------------
extern "C" void kernel_launch(void* const* d_in, const int* in_sizes, int n_in,
                              void* d_out, int out_size) {
    const float* dec_h = (const float*)d_in[0];
    const float* enc   = (const float*)d_in[1];
    const float* Wq    = (const float*)d_in[2];
    const float* Wk    = (const float*)d_in[3];
    const float* Wv    = (const float*)d_in[4];
    const float* W1    = (const float*)d_in[5];
    const float* W2    = (const float*)d_in[6];
    float* outp = (float*)d_out;

    k_qproj     <<<dim3(16, 8), 256>>>(dec_h, Wq);
    k_qtilde    <<<64, 256>>>(Wk);
    k_scores    <<<dim3(16, 16), 128>>>(enc);
    k_stats     <<<256, 256>>>();
    k_wsum_fixed<<<dim3(16, 32), 256>>>(enc);
    k_ctx       <<<dim3(16, 4), 256>>>(Wv);
    k_ffn1      <<<dim3(64, 4), 256>>>(dec_h, W1);
    k_ffn2      <<<dim3(16, 8), 256>>>(W2);
    k_fin       <<<16, 256>>>(outp);
}

// round 12
// speedup vs baseline: 1.0432x; 1.0432x over previous
#include <cuda_runtime.h>
#include <math.h>

// ---------------------------------------------------------------------------
// AttentionLayer: B=16, T=4096, D=1024, NH=16, HD=64, Tq=1.
// Folded formulation (K/V never materialized). 10 kernels:
//   K1 qproj  : q partials = dec_h @ Wq^T       (K-split 8)
//   K2 qtilde : qt[b,d,h] = SCALE * Wk_h^T q_h  (sums qproj partials)
//   K3 scores : sc[b,h,t] = enc . qt            (streams enc)
//   K4 stats  : per (b,h): (max, 1/sumexp) -> g_ms
//   K5 wsum   : u_part[c] = sum_t exp(sc-m)*inv * enc  (streams enc)
//   K6 combine: u = sum_c u_part                (wide streaming reduction)
//   K7 ctx    : ctx partials = Wv . u           (K-split 8)
//   K8 ffn1   : h partials = cat(dec_h, sum_8 ctx_p) @ W1^T  (K-split 4)
//   K9 ffn2   : o partials = silu(sum_4 h_p) @ W2^T          (K-split 8)
//   K10 fin   : out = sum_8 o partials
// ---------------------------------------------------------------------------

#define B_   16
#define T_   4096
#define D_   1024
#define NH_  16
#define HD_  64
#define NC_  32
#define TCH_ 128

typedef unsigned long long u64;

// scratch (no cudaMalloc allowed)
__device__ __align__(16) float  g_qp [8*B_*D_];       // qproj K-split partials
__device__ __align__(16) float  g_qt [B_*D_*NH_];     // [b][d][h] (scaled)
__device__ __align__(16) float  g_sc [B_*NH_*T_];     // scores [bh][t]
__device__ __align__(16) float2 g_ms [B_*NH_];        // (max, 1/sumexp)
__device__ __align__(16) float  g_up [NC_*B_*NH_*D_]; // wsum chunk partials
__device__ __align__(16) float  g_u  [B_*NH_*D_];     // [b][h][d]
__device__ __align__(16) float  g_cp [8*B_*D_];       // ctx K-split partials
__device__ __align__(16) float  g_h4 [4*B_*4*D_];     // ffn1 K-split partials
__device__ __align__(16) float  g_o8 [8*B_*D_];       // ffn2 K-split partials

// ---- packed f32x2 helpers -------------------------------------------------
__device__ __forceinline__ void fma2(u64 &acc, u64 a, u64 b) {
    asm("fma.rn.f32x2 %0, %1, %2, %0;" : "+l"(acc) : "l"(a), "l"(b));
}
__device__ __forceinline__ u64 pack2(float v) {
    u64 r; asm("mov.b64 %0, {%1, %1};" : "=l"(r) : "f"(v)); return r;
}
__device__ __forceinline__ u64 pack2b(float a, float b) {
    u64 r; asm("mov.b64 %0, {%1, %2};" : "=l"(r) : "f"(a), "f"(b)); return r;
}
__device__ __forceinline__ float2 unpack2(u64 v) {
    float2 r; asm("mov.b64 {%0, %1}, %2;" : "=f"(r.x), "=f"(r.y) : "l"(v)); return r;
}
__device__ __forceinline__ float wred(float s) {
    #pragma unroll
    for (int o = 16; o > 0; o >>= 1) s += __shfl_xor_sync(0xffffffffu, s, o);
    return s;
}

// ===========================================================================
// GEMM64: 256 threads, 64-j tile x all 16 b over NCHUNK*32 k. Double-buffered.
// ===========================================================================
#define GEMM64(WL4, XL, NCHUNK, KOFF)                                          \
    int tid = threadIdx.x, jj = tid >> 3, bp = tid & 7;                        \
    __shared__ u64  Ws[2][64][34];                                             \
    __shared__ float Xs[2][32][18];                                            \
    u64 accA = 0ull, accB = 0ull;                                              \
    const int r0 = tid >> 3, c0 = (tid * 4) & 31;                              \
    const int r1 = 32 + r0,  c1 = c0;                                          \
    const int xk = tid & 31, xb = tid >> 5;                                    \
    float4 w0, w1; float x0, x1;                                               \
    w0 = WL4(r0, (KOFF) + c0); w1 = WL4(r1, (KOFF) + c1);                      \
    x0 = XL(xb, (KOFF) + xk);  x1 = XL(xb + 8, (KOFF) + xk);                   \
    {                                                                          \
        ulonglong2* p0 = (ulonglong2*)&Ws[0][r0][c0];                          \
        p0[0] = make_ulonglong2(pack2(w0.x), pack2(w0.y));                     \
        p0[1] = make_ulonglong2(pack2(w0.z), pack2(w0.w));                     \
        ulonglong2* p1 = (ulonglong2*)&Ws[0][r1][c1];                          \
        p1[0] = make_ulonglong2(pack2(w1.x), pack2(w1.y));                     \
        p1[1] = make_ulonglong2(pack2(w1.z), pack2(w1.w));                     \
        Xs[0][xk][xb] = x0; Xs[0][xk][xb + 8] = x1;                            \
    }                                                                          \
    __syncthreads();                                                           \
    for (int ch = 0; ch < (NCHUNK); ch++) {                                    \
        int cur = ch & 1;                                                      \
        if (ch + 1 < (NCHUNK)) {                                               \
            int kb = (KOFF) + (ch + 1) * 32;                                   \
            w0 = WL4(r0, kb + c0); w1 = WL4(r1, kb + c1);                      \
            x0 = XL(xb, kb + xk);  x1 = XL(xb + 8, kb + xk);                   \
        }                                                                      \
        _Pragma("unroll")                                                      \
        for (int k = 0; k < 32; k++) {                                         \
            u64 xv = *(const u64*)&Xs[cur][k][bp * 2];                         \
            fma2(accA, Ws[cur][jj][k],      xv);                               \
            fma2(accB, Ws[cur][32 + jj][k], xv);                               \
        }                                                                      \
        if (ch + 1 < (NCHUNK)) {                                               \
            int nxt = cur ^ 1;                                                 \
            ulonglong2* p0 = (ulonglong2*)&Ws[nxt][r0][c0];                    \
            p0[0] = make_ulonglong2(pack2(w0.x), pack2(w0.y));                 \
            p0[1] = make_ulonglong2(pack2(w0.z), pack2(w0.w));                 \
            ulonglong2* p1 = (ulonglong2*)&Ws[nxt][r1][c1];                    \
            p1[0] = make_ulonglong2(pack2(w1.x), pack2(w1.y));                 \
            p1[1] = make_ulonglong2(pack2(w1.z), pack2(w1.w));                 \
            Xs[nxt][xk][xb] = x0; Xs[nxt][xk][xb + 8] = x1;                    \
        }                                                                      \
        __syncthreads();                                                       \
    }                                                                          \
    float2 vA = unpack2(accA), vB = unpack2(accB);

// ---------------------------------------------------------------------------
// K1: qproj partials.  grid (16 jb, 8 ks), 256 thr
__global__ __launch_bounds__(256) void k_qproj(const float* __restrict__ dec_h,
                                               const float* __restrict__ Wq) {
    int j0 = blockIdx.x * 64, ks = blockIdx.y;
#define WL4(r, k) (*(const float4*)&Wq[(size_t)(j0 + (r)) * D_ + (k)])
#define XLD(b, k) dec_h[(size_t)(b) * D_ + (k)]
    GEMM64(WL4, XLD, 4, ks * 128)
#undef WL4
#undef XLD
    float* o = g_qp + (size_t)ks * (B_ * D_);
    o[(size_t)(2 * bp)     * D_ + j0 + jj]      = vA.x;
    o[(size_t)(2 * bp + 1) * D_ + j0 + jj]      = vA.y;
    o[(size_t)(2 * bp)     * D_ + j0 + 32 + jj] = vB.x;
    o[(size_t)(2 * bp + 1) * D_ + j0 + 32 + jj] = vB.y;
}

// ---------------------------------------------------------------------------
// K2: qt[b][d][h] = SCALE * Wk_h^T q_h (sums the 8 qproj partials)
__global__ __launch_bounds__(256) void k_qtilde(const float* __restrict__ Wk) {
    int h = blockIdx.x >> 2, d0 = (blockIdx.x & 3) * 256, tid = threadIdx.x;
    __shared__ u64 qs2[64 * 8];          // [j][bpair]
    #pragma unroll
    for (int i = 0; i < 2; i++) {
        int idx = i * 256 + tid; int j = idx >> 3, bpp = idx & 7;
        float a = 0.f, bb = 0.f;
        #pragma unroll
        for (int ks = 0; ks < 8; ks++) {
            a  += g_qp[(size_t)ks * (B_ * D_) + (2 * bpp)     * D_ + h * HD_ + j];
            bb += g_qp[(size_t)ks * (B_ * D_) + (2 * bpp + 1) * D_ + h * HD_ + j];
        }
        qs2[j * 8 + bpp] = pack2b(a, bb);
    }
    __syncthreads();
    u64 acc[8];
    #pragma unroll
    for (int bp = 0; bp < 8; bp++) acc[bp] = 0ull;
    #pragma unroll 4
    for (int j = 0; j < HD_; j++) {
        u64 w2 = pack2(Wk[(size_t)(h * HD_ + j) * D_ + d0 + tid]);
        #pragma unroll
        for (int bp = 0; bp < 8; bp++) fma2(acc[bp], w2, qs2[j * 8 + bp]);
    }
    #pragma unroll
    for (int bp = 0; bp < 8; bp++) {
        float2 v = unpack2(acc[bp]);
        g_qt[(size_t)(2 * bp)     * D_ * NH_ + (d0 + tid) * NH_ + h] = 0.125f * v.x;
        g_qt[(size_t)(2 * bp + 1) * D_ * NH_ + (d0 + tid) * NH_ + h] = 0.125f * v.y;
    }
}

// ---------------------------------------------------------------------------
// K3: scores[b][h][t].  grid (16, 16), 128 thr (R6-proven).
__global__ __launch_bounds__(128) void k_scores(const float* __restrict__ enc) {
    const int b = blockIdx.x, t0 = blockIdx.y * 256, tid = threadIdx.x;
    __shared__ float es[2][16][258];
    __shared__ __align__(16) u64 qs2[2][16][8];
    const float* encb = enc + ((size_t)b * T_ + t0) * D_;
    const float* qtb  = g_qt + (size_t)b * D_ * NH_;

    const int lr = tid >> 2, lc = (tid & 3) * 4;
    const int qd = tid >> 3, qp8 = tid & 7;

    u64 accA[8], accB[8];
    #pragma unroll
    for (int hp = 0; hp < 8; hp++) { accA[hp] = 0ull; accB[hp] = 0ull; }

    float4 pe[8]; float2 pq;
    #pragma unroll
    for (int kk = 0; kk < 8; kk++)
        pe[kk] = *(const float4*)&encb[(size_t)(lr + 32 * kk) * D_ + lc];
    pq = *(const float2*)&qtb[(size_t)qd * NH_ + 2 * qp8];
    #pragma unroll
    for (int kk = 0; kk < 8; kk++) {
        int r = lr + 32 * kk;
        es[0][lc + 0][r] = pe[kk].x; es[0][lc + 1][r] = pe[kk].y;
        es[0][lc + 2][r] = pe[kk].z; es[0][lc + 3][r] = pe[kk].w;
    }
    qs2[0][qd][qp8] = pack2b(pq.x, pq.y);
    __syncthreads();

    for (int ch = 0; ch < 64; ch++) {
        int cur = ch & 1;
        if (ch + 1 < 64) {
            int dc = (ch + 1) * 16;
            #pragma unroll
            for (int kk = 0; kk < 8; kk++)
                pe[kk] = *(const float4*)&encb[(size_t)(lr + 32 * kk) * D_ + dc + lc];
            pq = *(const float2*)&qtb[(size_t)(dc + qd) * NH_ + 2 * qp8];
        }
        #pragma unroll
        for (int d = 0; d < 16; d++) {
            u64 e0 = pack2(es[cur][d][tid]);
            u64 e1 = pack2(es[cur][d][tid + 128]);
            const ulonglong2* qp = (const ulonglong2*)&qs2[cur][d][0];
            ulonglong2 qa = qp[0], qb = qp[1], qc = qp[2], qd2 = qp[3];
            fma2(accA[0], e0, qa.x); fma2(accB[0], e1, qa.x);
            fma2(accA[1], e0, qa.y); fma2(accB[1], e1, qa.y);
            fma2(accA[2], e0, qb.x); fma2(accB[2], e1, qb.x);
            fma2(accA[3], e0, qb.y); fma2(accB[3], e1, qb.y);
            fma2(accA[4], e0, qc.x); fma2(accB[4], e1, qc.x);
            fma2(accA[5], e0, qc.y); fma2(accB[5], e1, qc.y);
            fma2(accA[6], e0, qd2.x); fma2(accB[6], e1, qd2.x);
            fma2(accA[7], e0, qd2.y); fma2(accB[7], e1, qd2.y);
        }
        if (ch + 1 < 64) {
            int nxt = cur ^ 1;
            #pragma unroll
            for (int kk = 0; kk < 8; kk++) {
                int r = lr + 32 * kk;
                es[nxt][lc + 0][r] = pe[kk].x; es[nxt][lc + 1][r] = pe[kk].y;
                es[nxt][lc + 2][r] = pe[kk].z; es[nxt][lc + 3][r] = pe[kk].w;
            }
            qs2[nxt][qd][qp8] = pack2b(pq.x, pq.y);
        }
        __syncthreads();
    }
    int tA = t0 + tid, tB = t0 + 128 + tid;
    #pragma unroll
    for (int hp = 0; hp < 8; hp++) {
        float2 vA = unpack2(accA[hp]), vB = unpack2(accB[hp]);
        g_sc[((size_t)b * NH_ + 2 * hp    ) * T_ + tA] = vA.x;
        g_sc[((size_t)b * NH_ + 2 * hp + 1) * T_ + tA] = vA.y;
        g_sc[((size_t)b * NH_ + 2 * hp    ) * T_ + tB] = vB.x;
        g_sc[((size_t)b * NH_ + 2 * hp + 1) * T_ + tB] = vB.y;
    }
}

// ---------------------------------------------------------------------------
// K4: softmax STATS only: g_ms[bh] = (max, 1/sumexp).  grid 256, 256 thr.
__global__ __launch_bounds__(256) void k_stats() {
    int bh = blockIdx.x, tid = threadIdx.x;
    const float4* sc4 = (const float4*)(g_sc + (size_t)bh * T_);
    __shared__ float red[8];
    __shared__ float sbc;

    float4 v[4];
    float m = -1e30f;
    #pragma unroll
    for (int k = 0; k < 4; k++) {
        v[k] = sc4[(k << 8) + tid];
        m = fmaxf(m, fmaxf(fmaxf(v[k].x, v[k].y), fmaxf(v[k].z, v[k].w)));
    }
    #pragma unroll
    for (int o = 16; o > 0; o >>= 1) m = fmaxf(m, __shfl_xor_sync(0xffffffffu, m, o));
    if ((tid & 31) == 0) red[tid >> 5] = m;
    __syncthreads();
    if (tid == 0) {
        float mm = red[0];
        #pragma unroll
        for (int i = 1; i < 8; i++) mm = fmaxf(mm, red[i]);
        sbc = mm;
    }
    __syncthreads();
    m = sbc;
    float s = 0.f;
    #pragma unroll
    for (int k = 0; k < 4; k++) {
        s += (__expf(v[k].x - m) + __expf(v[k].y - m)) +
             (__expf(v[k].z - m) + __expf(v[k].w - m));
    }
    s = wred(s);
    __syncthreads();
    if ((tid & 31) == 0) red[tid >> 5] = s;
    __syncthreads();
    if (tid == 0) {
        float ss = 0.f;
        #pragma unroll
        for (int i = 0; i < 8; i++) ss += red[i];
        g_ms[bh] = make_float2(m, 1.f / ss);
    }
}

// ---------------------------------------------------------------------------
// K5: wsum partials; normalize folded into staging.  grid (16,32), 256 thr
__global__ __launch_bounds__(256) void k_wsum(const float* __restrict__ enc) {
    int b = blockIdx.x, c = blockIdx.y, tid = threadIdx.x;
    __shared__ float w_s[TCH_][18];
    #pragma unroll
    for (int i = 0; i < 8; i++) {
        int idx = (i << 8) + tid;
        int h = idx >> 7, t = idx & 127;
        float2 ms = g_ms[b * NH_ + h];
        float sc = g_sc[((size_t)b * NH_ + h) * T_ + c * TCH_ + t];
        w_s[t][h] = __expf(sc - ms.x) * ms.y;
    }
    __syncthreads();

    u64 u[4][8];
    #pragma unroll
    for (int d = 0; d < 4; d++)
        #pragma unroll
        for (int hp = 0; hp < 8; hp++) u[d][hp] = 0ull;

    const float4* e4 = (const float4*)(enc + ((size_t)b * T_ + (size_t)c * TCH_) * D_) + tid;
    #pragma unroll 8
    for (int t = 0; t < TCH_; t++) {
        float4 ev = e4[(size_t)t * (D_ / 4)];
        const u64* wp = (const u64*)&w_s[t][0];
        u64 e0 = pack2(ev.x), e1 = pack2(ev.y), e2 = pack2(ev.z), e3 = pack2(ev.w);
        #pragma unroll
        for (int hp = 0; hp < 8; hp++) {
            u64 w2 = wp[hp];
            fma2(u[0][hp], e0, w2);
            fma2(u[1][hp], e1, w2);
            fma2(u[2][hp], e2, w2);
            fma2(u[3][hp], e3, w2);
        }
    }
    #pragma unroll
    for (int hp = 0; hp < 8; hp++) {
        float2 a0 = unpack2(u[0][hp]), a1 = unpack2(u[1][hp]),
               a2 = unpack2(u[2][hp]), a3 = unpack2(u[3][hp]);
        float4 lo = make_float4(a0.x, a1.x, a2.x, a3.x);
        float4 hi = make_float4(a0.y, a1.y, a2.y, a3.y);
        size_t base = (((size_t)c * B_ + b) * NH_) * D_ + 4 * tid;
        *(float4*)(g_up + base + (size_t)(2 * hp)     * D_) = lo;
        *(float4*)(g_up + base + (size_t)(2 * hp + 1) * D_) = hi;
    }
}

// ---------------------------------------------------------------------------
// K6: u = sum_c u_part   (wide streaming reduction, 1024 CTAs)
__global__ __launch_bounds__(256) void k_combine() {
    int idx = blockIdx.x * 256 + threadIdx.x;
    float s = 0.f;
    #pragma unroll
    for (int c = 0; c < NC_; c++) s += g_up[(size_t)c * (B_ * NH_ * D_) + idx];
    g_u[idx] = s;
}

// ---------------------------------------------------------------------------
// K7: ctx partials = Wv . u     grid (16 jb, 8 ks)
__global__ __launch_bounds__(256) void k_ctx(const float* __restrict__ Wv) {
    int j0 = blockIdx.x * 64, ks = blockIdx.y;
    int h  = blockIdx.x;
#define WL4(r, k) (*(const float4*)&Wv[(size_t)(j0 + (r)) * D_ + (k)])
#define XLD(b, k) g_u[((size_t)(b) * NH_ + h) * D_ + (k)]
    GEMM64(WL4, XLD, 4, ks * 128)
#undef WL4
#undef XLD
    float* o = g_cp + (size_t)ks * (B_ * D_);
    o[(size_t)(2 * bp)     * D_ + j0 + jj]      = vA.x;
    o[(size_t)(2 * bp + 1) * D_ + j0 + jj]      = vA.y;
    o[(size_t)(2 * bp)     * D_ + j0 + 32 + jj] = vB.x;
    o[(size_t)(2 * bp + 1) * D_ + j0 + 32 + jj] = vB.y;
}

// ---------------------------------------------------------------------------
// K8: ffn1 partials = cat(dec_h, sum_8 ctx_p) @ W1^T   grid (64 jb, 4 ks)
__global__ __launch_bounds__(256) void k_ffn1(const float* __restrict__ dec_h,
                                              const float* __restrict__ W1) {
    int j0 = blockIdx.x * 64, ks = blockIdx.y;
#define WL4(r, k) (*(const float4*)&W1[(size_t)(j0 + (r)) * (2 * D_) + (k)])
#define XLD(b, k) ((k) < D_ ? dec_h[(size_t)(b) * D_ + (k)]                    \
    : (((g_cp[(size_t)(b) * D_ + (k) - D_] +                                   \
         g_cp[(size_t)(B_ * D_) + (b) * D_ + (k) - D_]) +                      \
        (g_cp[(size_t)(2 * B_ * D_) + (b) * D_ + (k) - D_] +                   \
         g_cp[(size_t)(3 * B_ * D_) + (b) * D_ + (k) - D_])) +                 \
       ((g_cp[(size_t)(4 * B_ * D_) + (b) * D_ + (k) - D_] +                   \
         g_cp[(size_t)(5 * B_ * D_) + (b) * D_ + (k) - D_]) +                  \
        (g_cp[(size_t)(6 * B_ * D_) + (b) * D_ + (k) - D_] +                   \
         g_cp[(size_t)(7 * B_ * D_) + (b) * D_ + (k) - D_]))))
    GEMM64(WL4, XLD, 16, ks * 512)
#undef WL4
#undef XLD
    float* o = g_h4 + (size_t)ks * (B_ * 4 * D_);
    o[(size_t)(2 * bp)     * (4 * D_) + j0 + jj]      = vA.x;
    o[(size_t)(2 * bp + 1) * (4 * D_) + j0 + jj]      = vA.y;
    o[(size_t)(2 * bp)     * (4 * D_) + j0 + 32 + jj] = vB.x;
    o[(size_t)(2 * bp + 1) * (4 * D_) + j0 + 32 + jj] = vB.y;
}

// ---------------------------------------------------------------------------
// K9: ffn2 partials = silu(sum_4 h_p) @ W2^T   grid (16 jb, 8 ks)
__global__ __launch_bounds__(256) void k_ffn2(const float* __restrict__ W2) {
    int j0 = blockIdx.x * 64, ks = blockIdx.y;
#define WL4(r, k) (*(const float4*)&W2[(size_t)(j0 + (r)) * (4 * D_) + (k)])
#define XLD(b, k) ({                                                           \
        float _x = (g_h4[(size_t)(b) * (4 * D_) + (k)] +                       \
                    g_h4[(size_t)(B_ * 4 * D_) + (b) * (4 * D_) + (k)]) +      \
                   (g_h4[(size_t)(2 * B_ * 4 * D_) + (b) * (4 * D_) + (k)] +   \
                    g_h4[(size_t)(3 * B_ * 4 * D_) + (b) * (4 * D_) + (k)]);   \
        _x / (1.f + __expf(-_x)); })
    GEMM64(WL4, XLD, 16, ks * 512)
#undef WL4
#undef XLD
    float* o = g_o8 + (size_t)ks * (B_ * D_);
    o[(size_t)(2 * bp)     * D_ + j0 + jj]      = vA.x;
    o[(size_t)(2 * bp + 1) * D_ + j0 + jj]      = vA.y;
    o[(size_t)(2 * bp)     * D_ + j0 + 32 + jj] = vB.x;
    o[(size_t)(2 * bp + 1) * D_ + j0 + 32 + jj] = vB.y;
}

// ---------------------------------------------------------------------------
// K10: out = sum of 8 ffn2 partials   grid 16, 256 thr, float4
__global__ __launch_bounds__(256) void k_fin(float* __restrict__ outp) {
    int i = (blockIdx.x * 256 + threadIdx.x) * 4;
    float4 s = *(const float4*)&g_o8[i];
    #pragma unroll
    for (int ks = 1; ks < 8; ks++) {
        float4 p = *(const float4*)&g_o8[(size_t)ks * (B_ * D_) + i];
        s.x += p.x; s.y += p.y; s.z += p.z; s.w += p.w;
    }
    *(float4*)&outp[i] = s;
}

// ---------------------------------------------------------------------------
extern "C" void kernel_launch(void* const* d_in, const int* in_sizes, int n_in,
                              void* d_out, int out_size) {
    const float* dec_h = (const float*)d_in[0];
    const float* enc   = (const float*)d_in[1];
    const float* Wq    = (const float*)d_in[2];
    const float* Wk    = (const float*)d_in[3];
    const float* Wv    = (const float*)d_in[4];
    const float* W1    = (const float*)d_in[5];
    const float* W2    = (const float*)d_in[6];
    float* outp = (float*)d_out;

    k_qproj  <<<dim3(16, 8), 256>>>(dec_h, Wq);
    k_qtilde <<<64, 256>>>(Wk);
    k_scores <<<dim3(16, 16), 128>>>(enc);
    k_stats  <<<256, 256>>>();
    k_wsum   <<<dim3(16, 32), 256>>>(enc);
    k_combine<<<1024, 256>>>();
    k_ctx    <<<dim3(16, 8), 256>>>(Wv);
    k_ffn1   <<<dim3(64, 4), 256>>>(dec_h, W1);
    k_ffn2   <<<dim3(16, 8), 256>>>(W2);
    k_fin    <<<16, 256>>>(outp);
}

// round 13
// speedup vs baseline: 1.0769x; 1.0323x over previous
#include <cuda_runtime.h>
#include <math.h>

// ---------------------------------------------------------------------------
// AttentionLayer: B=16, T=4096, D=1024, NH=16, HD=64, Tq=1.
// Folded formulation (K/V never materialized). 10 kernels:
//   K1 qproj  : q partials = dec_h @ Wq^T       (K-split 8)
//   K2 qtilde : qt[b,d,h] = SCALE * Wk_h^T q_h  (128 CTAs)
//   K3 scores : sc_part[z][b,h,t] = enc[:,dz] . qt[dz,:]  (K-split 2 over d)
//   K4 stats  : per (b,h): (max, 1/sumexp) of (p0+p1) -> g_ms
//   K5 wsum   : u_part[c] = sum_t exp(p0+p1-m)*inv * enc  (streams enc)
//   K6 combine: u = sum_c u_part
//   K7 ctx    : ctx partials = Wv . u           (K-split 8)
//   K8 ffn1   : h partials = cat(dec_h, sum_8 ctx_p) @ W1^T  (K-split 4)
//   K9 ffn2   : o partials = silu(sum_4 h_p) @ W2^T          (K-split 8)
//   K10 fin   : out = sum_8 o partials
// ---------------------------------------------------------------------------

#define B_   16
#define T_   4096
#define D_   1024
#define NH_  16
#define HD_  64
#define NC_  32
#define TCH_ 128
#define SCP_ ((size_t)B_*NH_*T_)     // one score-partial plane

typedef unsigned long long u64;

// scratch (no cudaMalloc allowed)
__device__ __align__(16) float  g_qp [8*B_*D_];       // qproj K-split partials
__device__ __align__(16) float  g_qt [B_*D_*NH_];     // [b][d][h] (scaled)
__device__ __align__(16) float  g_scp[2*B_*NH_*T_];   // score partials [z][bh][t]
__device__ __align__(16) float2 g_ms [B_*NH_];        // (max, 1/sumexp)
__device__ __align__(16) float  g_up [NC_*B_*NH_*D_]; // wsum chunk partials
__device__ __align__(16) float  g_u  [B_*NH_*D_];     // [b][h][d]
__device__ __align__(16) float  g_cp [8*B_*D_];       // ctx K-split partials
__device__ __align__(16) float  g_h4 [4*B_*4*D_];     // ffn1 K-split partials
__device__ __align__(16) float  g_o8 [8*B_*D_];       // ffn2 K-split partials

// ---- packed f32x2 helpers -------------------------------------------------
__device__ __forceinline__ void fma2(u64 &acc, u64 a, u64 b) {
    asm("fma.rn.f32x2 %0, %1, %2, %0;" : "+l"(acc) : "l"(a), "l"(b));
}
__device__ __forceinline__ u64 pack2(float v) {
    u64 r; asm("mov.b64 %0, {%1, %1};" : "=l"(r) : "f"(v)); return r;
}
__device__ __forceinline__ u64 pack2b(float a, float b) {
    u64 r; asm("mov.b64 %0, {%1, %2};" : "=l"(r) : "f"(a), "f"(b)); return r;
}
__device__ __forceinline__ float2 unpack2(u64 v) {
    float2 r; asm("mov.b64 {%0, %1}, %2;" : "=f"(r.x), "=f"(r.y) : "l"(v)); return r;
}
__device__ __forceinline__ float wred(float s) {
    #pragma unroll
    for (int o = 16; o > 0; o >>= 1) s += __shfl_xor_sync(0xffffffffu, s, o);
    return s;
}

// ===========================================================================
// GEMM64: 256 threads, 64-j tile x all 16 b over NCHUNK*32 k. Double-buffered.
// ===========================================================================
#define GEMM64(WL4, XL, NCHUNK, KOFF)                                          \
    int tid = threadIdx.x, jj = tid >> 3, bp = tid & 7;                        \
    __shared__ u64  Ws[2][64][34];                                             \
    __shared__ float Xs[2][32][18];                                            \
    u64 accA = 0ull, accB = 0ull;                                              \
    const int r0 = tid >> 3, c0 = (tid * 4) & 31;                              \
    const int r1 = 32 + r0,  c1 = c0;                                          \
    const int xk = tid & 31, xb = tid >> 5;                                    \
    float4 w0, w1; float x0, x1;                                               \
    w0 = WL4(r0, (KOFF) + c0); w1 = WL4(r1, (KOFF) + c1);                      \
    x0 = XL(xb, (KOFF) + xk);  x1 = XL(xb + 8, (KOFF) + xk);                   \
    {                                                                          \
        ulonglong2* p0 = (ulonglong2*)&Ws[0][r0][c0];                          \
        p0[0] = make_ulonglong2(pack2(w0.x), pack2(w0.y));                     \
        p0[1] = make_ulonglong2(pack2(w0.z), pack2(w0.w));                     \
        ulonglong2* p1 = (ulonglong2*)&Ws[0][r1][c1];                          \
        p1[0] = make_ulonglong2(pack2(w1.x), pack2(w1.y));                     \
        p1[1] = make_ulonglong2(pack2(w1.z), pack2(w1.w));                     \
        Xs[0][xk][xb] = x0; Xs[0][xk][xb + 8] = x1;                            \
    }                                                                          \
    __syncthreads();                                                           \
    for (int ch = 0; ch < (NCHUNK); ch++) {                                    \
        int cur = ch & 1;                                                      \
        if (ch + 1 < (NCHUNK)) {                                               \
            int kb = (KOFF) + (ch + 1) * 32;                                   \
            w0 = WL4(r0, kb + c0); w1 = WL4(r1, kb + c1);                      \
            x0 = XL(xb, kb + xk);  x1 = XL(xb + 8, kb + xk);                   \
        }                                                                      \
        _Pragma("unroll")                                                      \
        for (int k = 0; k < 32; k++) {                                         \
            u64 xv = *(const u64*)&Xs[cur][k][bp * 2];                         \
            fma2(accA, Ws[cur][jj][k],      xv);                               \
            fma2(accB, Ws[cur][32 + jj][k], xv);                               \
        }                                                                      \
        if (ch + 1 < (NCHUNK)) {                                               \
            int nxt = cur ^ 1;                                                 \
            ulonglong2* p0 = (ulonglong2*)&Ws[nxt][r0][c0];                    \
            p0[0] = make_ulonglong2(pack2(w0.x), pack2(w0.y));                 \
            p0[1] = make_ulonglong2(pack2(w0.z), pack2(w0.w));                 \
            ulonglong2* p1 = (ulonglong2*)&Ws[nxt][r1][c1];                    \
            p1[0] = make_ulonglong2(pack2(w1.x), pack2(w1.y));                 \
            p1[1] = make_ulonglong2(pack2(w1.z), pack2(w1.w));                 \
            Xs[nxt][xk][xb] = x0; Xs[nxt][xk][xb + 8] = x1;                    \
        }                                                                      \
        __syncthreads();                                                       \
    }                                                                          \
    float2 vA = unpack2(accA), vB = unpack2(accB);

// ---------------------------------------------------------------------------
// K1: qproj partials.  grid (16 jb, 8 ks), 256 thr
__global__ __launch_bounds__(256) void k_qproj(const float* __restrict__ dec_h,
                                               const float* __restrict__ Wq) {
    int j0 = blockIdx.x * 64, ks = blockIdx.y;
#define WL4(r, k) (*(const float4*)&Wq[(size_t)(j0 + (r)) * D_ + (k)])
#define XLD(b, k) dec_h[(size_t)(b) * D_ + (k)]
    GEMM64(WL4, XLD, 4, ks * 128)
#undef WL4
#undef XLD
    float* o = g_qp + (size_t)ks * (B_ * D_);
    o[(size_t)(2 * bp)     * D_ + j0 + jj]      = vA.x;
    o[(size_t)(2 * bp + 1) * D_ + j0 + jj]      = vA.y;
    o[(size_t)(2 * bp)     * D_ + j0 + 32 + jj] = vB.x;
    o[(size_t)(2 * bp + 1) * D_ + j0 + 32 + jj] = vB.y;
}

// ---------------------------------------------------------------------------
// K2: qt[b][d][h] = SCALE * Wk_h^T q_h (sums 8 qproj partials)
// grid 128 (h*8 + eighth), 128 thr (d-eighths of 128)
__global__ __launch_bounds__(128) void k_qtilde(const float* __restrict__ Wk) {
    int h = blockIdx.x >> 3, d0 = (blockIdx.x & 7) * 128, tid = threadIdx.x;
    __shared__ u64 qs2[64 * 8];          // [j][bpair]
    #pragma unroll
    for (int i = 0; i < 4; i++) {
        int idx = i * 128 + tid; int j = idx >> 3, bpp = idx & 7;
        float a = 0.f, bb = 0.f;
        #pragma unroll
        for (int ks = 0; ks < 8; ks++) {
            a  += g_qp[(size_t)ks * (B_ * D_) + (2 * bpp)     * D_ + h * HD_ + j];
            bb += g_qp[(size_t)ks * (B_ * D_) + (2 * bpp + 1) * D_ + h * HD_ + j];
        }
        qs2[j * 8 + bpp] = pack2b(a, bb);
    }
    __syncthreads();
    u64 acc[8];
    #pragma unroll
    for (int bp = 0; bp < 8; bp++) acc[bp] = 0ull;
    #pragma unroll 4
    for (int j = 0; j < HD_; j++) {
        u64 w2 = pack2(Wk[(size_t)(h * HD_ + j) * D_ + d0 + tid]);
        #pragma unroll
        for (int bp = 0; bp < 8; bp++) fma2(acc[bp], w2, qs2[j * 8 + bp]);
    }
    #pragma unroll
    for (int bp = 0; bp < 8; bp++) {
        float2 v = unpack2(acc[bp]);
        g_qt[(size_t)(2 * bp)     * D_ * NH_ + (d0 + tid) * NH_ + h] = 0.125f * v.x;
        g_qt[(size_t)(2 * bp + 1) * D_ * NH_ + (d0 + tid) * NH_ + h] = 0.125f * v.y;
    }
}

// ---------------------------------------------------------------------------
// K3: score PARTIALS over d-half.  grid (16, 16, 2), 128 thr.
// Inner structure identical to R6-proven k_scores; 32 chunks per CTA.
__global__ __launch_bounds__(128) void k_scores(const float* __restrict__ enc) {
    const int b = blockIdx.x, t0 = blockIdx.y * 256, zz = blockIdx.z;
    const int tid = threadIdx.x;
    const int dbase = zz * 512;
    __shared__ float es[2][16][258];
    __shared__ __align__(16) u64 qs2[2][16][8];
    const float* encb = enc + ((size_t)b * T_ + t0) * D_;
    const float* qtb  = g_qt + (size_t)b * D_ * NH_;

    const int lr = tid >> 2, lc = (tid & 3) * 4;
    const int qd = tid >> 3, qp8 = tid & 7;

    u64 accA[8], accB[8];
    #pragma unroll
    for (int hp = 0; hp < 8; hp++) { accA[hp] = 0ull; accB[hp] = 0ull; }

    float4 pe[8]; float2 pq;
    #pragma unroll
    for (int kk = 0; kk < 8; kk++)
        pe[kk] = *(const float4*)&encb[(size_t)(lr + 32 * kk) * D_ + dbase + lc];
    pq = *(const float2*)&qtb[(size_t)(dbase + qd) * NH_ + 2 * qp8];
    #pragma unroll
    for (int kk = 0; kk < 8; kk++) {
        int r = lr + 32 * kk;
        es[0][lc + 0][r] = pe[kk].x; es[0][lc + 1][r] = pe[kk].y;
        es[0][lc + 2][r] = pe[kk].z; es[0][lc + 3][r] = pe[kk].w;
    }
    qs2[0][qd][qp8] = pack2b(pq.x, pq.y);
    __syncthreads();

    for (int ch = 0; ch < 32; ch++) {
        int cur = ch & 1;
        if (ch + 1 < 32) {
            int dc = dbase + (ch + 1) * 16;
            #pragma unroll
            for (int kk = 0; kk < 8; kk++)
                pe[kk] = *(const float4*)&encb[(size_t)(lr + 32 * kk) * D_ + dc + lc];
            pq = *(const float2*)&qtb[(size_t)(dc + qd) * NH_ + 2 * qp8];
        }
        #pragma unroll
        for (int d = 0; d < 16; d++) {
            u64 e0 = pack2(es[cur][d][tid]);
            u64 e1 = pack2(es[cur][d][tid + 128]);
            const ulonglong2* qp = (const ulonglong2*)&qs2[cur][d][0];
            ulonglong2 qa = qp[0], qb = qp[1], qc = qp[2], qd2 = qp[3];
            fma2(accA[0], e0, qa.x); fma2(accB[0], e1, qa.x);
            fma2(accA[1], e0, qa.y); fma2(accB[1], e1, qa.y);
            fma2(accA[2], e0, qb.x); fma2(accB[2], e1, qb.x);
            fma2(accA[3], e0, qb.y); fma2(accB[3], e1, qb.y);
            fma2(accA[4], e0, qc.x); fma2(accB[4], e1, qc.x);
            fma2(accA[5], e0, qc.y); fma2(accB[5], e1, qc.y);
            fma2(accA[6], e0, qd2.x); fma2(accB[6], e1, qd2.x);
            fma2(accA[7], e0, qd2.y); fma2(accB[7], e1, qd2.y);
        }
        if (ch + 1 < 32) {
            int nxt = cur ^ 1;
            #pragma unroll
            for (int kk = 0; kk < 8; kk++) {
                int r = lr + 32 * kk;
                es[nxt][lc + 0][r] = pe[kk].x; es[nxt][lc + 1][r] = pe[kk].y;
                es[nxt][lc + 2][r] = pe[kk].z; es[nxt][lc + 3][r] = pe[kk].w;
            }
            qs2[nxt][qd][qp8] = pack2b(pq.x, pq.y);
        }
        __syncthreads();
    }
    int tA = t0 + tid, tB = t0 + 128 + tid;
    float* sco = g_scp + (size_t)zz * SCP_;
    #pragma unroll
    for (int hp = 0; hp < 8; hp++) {
        float2 vA = unpack2(accA[hp]), vB = unpack2(accB[hp]);
        sco[((size_t)b * NH_ + 2 * hp    ) * T_ + tA] = vA.x;
        sco[((size_t)b * NH_ + 2 * hp + 1) * T_ + tA] = vA.y;
        sco[((size_t)b * NH_ + 2 * hp    ) * T_ + tB] = vB.x;
        sco[((size_t)b * NH_ + 2 * hp + 1) * T_ + tB] = vB.y;
    }
}

// ---------------------------------------------------------------------------
// K4: stats over sc = p0+p1: g_ms[bh] = (max, 1/sumexp).  grid 256, 256 thr.
__global__ __launch_bounds__(256) void k_stats() {
    int bh = blockIdx.x, tid = threadIdx.x;
    const float4* p04 = (const float4*)(g_scp + (size_t)bh * T_);
    const float4* p14 = (const float4*)(g_scp + SCP_ + (size_t)bh * T_);
    __shared__ float red[8];
    __shared__ float sbc;

    float4 v[4];
    float m = -1e30f;
    #pragma unroll
    for (int k = 0; k < 4; k++) {
        float4 a = p04[(k << 8) + tid], b4 = p14[(k << 8) + tid];
        v[k] = make_float4(a.x + b4.x, a.y + b4.y, a.z + b4.z, a.w + b4.w);
        m = fmaxf(m, fmaxf(fmaxf(v[k].x, v[k].y), fmaxf(v[k].z, v[k].w)));
    }
    #pragma unroll
    for (int o = 16; o > 0; o >>= 1) m = fmaxf(m, __shfl_xor_sync(0xffffffffu, m, o));
    if ((tid & 31) == 0) red[tid >> 5] = m;
    __syncthreads();
    if (tid == 0) {
        float mm = red[0];
        #pragma unroll
        for (int i = 1; i < 8; i++) mm = fmaxf(mm, red[i]);
        sbc = mm;
    }
    __syncthreads();
    m = sbc;
    float s = 0.f;
    #pragma unroll
    for (int k = 0; k < 4; k++) {
        s += (__expf(v[k].x - m) + __expf(v[k].y - m)) +
             (__expf(v[k].z - m) + __expf(v[k].w - m));
    }
    s = wred(s);
    __syncthreads();
    if ((tid & 31) == 0) red[tid >> 5] = s;
    __syncthreads();
    if (tid == 0) {
        float ss = 0.f;
        #pragma unroll
        for (int i = 0; i < 8; i++) ss += red[i];
        g_ms[bh] = make_float2(m, 1.f / ss);
    }
}

// ---------------------------------------------------------------------------
// K5: wsum partials; sc = p0+p1, normalize folded.  grid (16,32), 256 thr
__global__ __launch_bounds__(256) void k_wsum(const float* __restrict__ enc) {
    int b = blockIdx.x, c = blockIdx.y, tid = threadIdx.x;
    __shared__ float w_s[TCH_][18];
    #pragma unroll
    for (int i = 0; i < 8; i++) {
        int idx = (i << 8) + tid;
        int h = idx >> 7, t = idx & 127;
        float2 ms = g_ms[b * NH_ + h];
        size_t si = ((size_t)b * NH_ + h) * T_ + c * TCH_ + t;
        float sc = g_scp[si] + g_scp[SCP_ + si];
        w_s[t][h] = __expf(sc - ms.x) * ms.y;
    }
    __syncthreads();

    u64 u[4][8];
    #pragma unroll
    for (int d = 0; d < 4; d++)
        #pragma unroll
        for (int hp = 0; hp < 8; hp++) u[d][hp] = 0ull;

    const float4* e4 = (const float4*)(enc + ((size_t)b * T_ + (size_t)c * TCH_) * D_) + tid;
    #pragma unroll 8
    for (int t = 0; t < TCH_; t++) {
        float4 ev = e4[(size_t)t * (D_ / 4)];
        const u64* wp = (const u64*)&w_s[t][0];
        u64 e0 = pack2(ev.x), e1 = pack2(ev.y), e2 = pack2(ev.z), e3 = pack2(ev.w);
        #pragma unroll
        for (int hp = 0; hp < 8; hp++) {
            u64 w2 = wp[hp];
            fma2(u[0][hp], e0, w2);
            fma2(u[1][hp], e1, w2);
            fma2(u[2][hp], e2, w2);
            fma2(u[3][hp], e3, w2);
        }
    }
    #pragma unroll
    for (int hp = 0; hp < 8; hp++) {
        float2 a0 = unpack2(u[0][hp]), a1 = unpack2(u[1][hp]),
               a2 = unpack2(u[2][hp]), a3 = unpack2(u[3][hp]);
        float4 lo = make_float4(a0.x, a1.x, a2.x, a3.x);
        float4 hi = make_float4(a0.y, a1.y, a2.y, a3.y);
        size_t base = (((size_t)c * B_ + b) * NH_) * D_ + 4 * tid;
        *(float4*)(g_up + base + (size_t)(2 * hp)     * D_) = lo;
        *(float4*)(g_up + base + (size_t)(2 * hp + 1) * D_) = hi;
    }
}

// ---------------------------------------------------------------------------
// K6: u = sum_c u_part   (wide streaming reduction, 1024 CTAs)
__global__ __launch_bounds__(256) void k_combine() {
    int idx = blockIdx.x * 256 + threadIdx.x;
    float s = 0.f;
    #pragma unroll
    for (int c = 0; c < NC_; c++) s += g_up[(size_t)c * (B_ * NH_ * D_) + idx];
    g_u[idx] = s;
}

// ---------------------------------------------------------------------------
// K7: ctx partials = Wv . u     grid (16 jb, 8 ks)
__global__ __launch_bounds__(256) void k_ctx(const float* __restrict__ Wv) {
    int j0 = blockIdx.x * 64, ks = blockIdx.y;
    int h  = blockIdx.x;
#define WL4(r, k) (*(const float4*)&Wv[(size_t)(j0 + (r)) * D_ + (k)])
#define XLD(b, k) g_u[((size_t)(b) * NH_ + h) * D_ + (k)]
    GEMM64(WL4, XLD, 4, ks * 128)
#undef WL4
#undef XLD
    float* o = g_cp + (size_t)ks * (B_ * D_);
    o[(size_t)(2 * bp)     * D_ + j0 + jj]      = vA.x;
    o[(size_t)(2 * bp + 1) * D_ + j0 + jj]      = vA.y;
    o[(size_t)(2 * bp)     * D_ + j0 + 32 + jj] = vB.x;
    o[(size_t)(2 * bp + 1) * D_ + j0 + 32 + jj] = vB.y;
}

// ---------------------------------------------------------------------------
// K8: ffn1 partials = cat(dec_h, sum_8 ctx_p) @ W1^T   grid (64 jb, 4 ks)
__global__ __launch_bounds__(256) void k_ffn1(const float* __restrict__ dec_h,
                                              const float* __restrict__ W1) {
    int j0 = blockIdx.x * 64, ks = blockIdx.y;
#define WL4(r, k) (*(const float4*)&W1[(size_t)(j0 + (r)) * (2 * D_) + (k)])
#define XLD(b, k) ((k) < D_ ? dec_h[(size_t)(b) * D_ + (k)]                    \
    : (((g_cp[(size_t)(b) * D_ + (k) - D_] +                                   \
         g_cp[(size_t)(B_ * D_) + (b) * D_ + (k) - D_]) +                      \
        (g_cp[(size_t)(2 * B_ * D_) + (b) * D_ + (k) - D_] +                   \
         g_cp[(size_t)(3 * B_ * D_) + (b) * D_ + (k) - D_])) +                 \
       ((g_cp[(size_t)(4 * B_ * D_) + (b) * D_ + (k) - D_] +                   \
         g_cp[(size_t)(5 * B_ * D_) + (b) * D_ + (k) - D_]) +                  \
        (g_cp[(size_t)(6 * B_ * D_) + (b) * D_ + (k) - D_] +                   \
         g_cp[(size_t)(7 * B_ * D_) + (b) * D_ + (k) - D_]))))
    GEMM64(WL4, XLD, 16, ks * 512)
#undef WL4
#undef XLD
    float* o = g_h4 + (size_t)ks * (B_ * 4 * D_);
    o[(size_t)(2 * bp)     * (4 * D_) + j0 + jj]      = vA.x;
    o[(size_t)(2 * bp + 1) * (4 * D_) + j0 + jj]      = vA.y;
    o[(size_t)(2 * bp)     * (4 * D_) + j0 + 32 + jj] = vB.x;
    o[(size_t)(2 * bp + 1) * (4 * D_) + j0 + 32 + jj] = vB.y;
}

// ---------------------------------------------------------------------------
// K9: ffn2 partials = silu(sum_4 h_p) @ W2^T   grid (16 jb, 8 ks)
__global__ __launch_bounds__(256) void k_ffn2(const float* __restrict__ W2) {
    int j0 = blockIdx.x * 64, ks = blockIdx.y;
#define WL4(r, k) (*(const float4*)&W2[(size_t)(j0 + (r)) * (4 * D_) + (k)])
#define XLD(b, k) ({                                                           \
        float _x = (g_h4[(size_t)(b) * (4 * D_) + (k)] +                       \
                    g_h4[(size_t)(B_ * 4 * D_) + (b) * (4 * D_) + (k)]) +      \
                   (g_h4[(size_t)(2 * B_ * 4 * D_) + (b) * (4 * D_) + (k)] +   \
                    g_h4[(size_t)(3 * B_ * 4 * D_) + (b) * (4 * D_) + (k)]);   \
        _x / (1.f + __expf(-_x)); })
    GEMM64(WL4, XLD, 16, ks * 512)
#undef WL4
#undef XLD
    float* o = g_o8 + (size_t)ks * (B_ * D_);
    o[(size_t)(2 * bp)     * D_ + j0 + jj]      = vA.x;
    o[(size_t)(2 * bp + 1) * D_ + j0 + jj]      = vA.y;
    o[(size_t)(2 * bp)     * D_ + j0 + 32 + jj] = vB.x;
    o[(size_t)(2 * bp + 1) * D_ + j0 + 32 + jj] = vB.y;
}

// ---------------------------------------------------------------------------
// K10: out = sum of 8 ffn2 partials   grid 16, 256 thr, float4
__global__ __launch_bounds__(256) void k_fin(float* __restrict__ outp) {
    int i = (blockIdx.x * 256 + threadIdx.x) * 4;
    float4 s = *(const float4*)&g_o8[i];
    #pragma unroll
    for (int ks = 1; ks < 8; ks++) {
        float4 p = *(const float4*)&g_o8[(size_t)ks * (B_ * D_) + i];
        s.x += p.x; s.y += p.y; s.z += p.z; s.w += p.w;
    }
    *(float4*)&outp[i] = s;
}

// ---------------------------------------------------------------------------
extern "C" void kernel_launch(void* const* d_in, const int* in_sizes, int n_in,
                              void* d_out, int out_size) {
    const float* dec_h = (const float*)d_in[0];
    const float* enc   = (const float*)d_in[1];
    const float* Wq    = (const float*)d_in[2];
    const float* Wk    = (const float*)d_in[3];
    const float* Wv    = (const float*)d_in[4];
    const float* W1    = (const float*)d_in[5];
    const float* W2    = (const float*)d_in[6];
    float* outp = (float*)d_out;

    k_qproj  <<<dim3(16, 8), 256>>>(dec_h, Wq);
    k_qtilde <<<128, 128>>>(Wk);
    k_scores <<<dim3(16, 16, 2), 128>>>(enc);
    k_stats  <<<256, 256>>>();
    k_wsum   <<<dim3(16, 32), 256>>>(enc);
    k_combine<<<1024, 256>>>();
    k_ctx    <<<dim3(16, 8), 256>>>(Wv);
    k_ffn1   <<<dim3(64, 4), 256>>>(dec_h, W1);
    k_ffn2   <<<dim3(16, 8), 256>>>(W2);
    k_fin    <<<16, 256>>>(outp);
}

// round 14
// speedup vs baseline: 1.2553x; 1.1657x over previous
#include <cuda_runtime.h>
#include <math.h>
#include <stdint.h>

// ---------------------------------------------------------------------------
// AttentionLayer: B=16, T=4096, D=1024, NH=16, HD=64, Tq=1.
// Folded formulation (K/V never materialized). 10 kernels.
// R14: k_scores uses tf32 mma.sync (m16n8k8) -> FMA-pipe work off-loaded to
// tensor cores; scores back to a single full plane g_sc.
// ---------------------------------------------------------------------------

#define B_   16
#define T_   4096
#define D_   1024
#define NH_  16
#define HD_  64
#define NC_  32
#define TCH_ 128

typedef unsigned long long u64;

// scratch (no cudaMalloc allowed)
__device__ __align__(16) float  g_qp [8*B_*D_];       // qproj K-split partials
__device__ __align__(16) float  g_qt [B_*D_*NH_];     // [b][d][h] (scaled)
__device__ __align__(16) float  g_sc [B_*NH_*T_];     // scores [bh][t]
__device__ __align__(16) float2 g_ms [B_*NH_];        // (max, 1/sumexp)
__device__ __align__(16) float  g_up [NC_*B_*NH_*D_]; // wsum chunk partials
__device__ __align__(16) float  g_u  [B_*NH_*D_];     // [b][h][d]
__device__ __align__(16) float  g_cp [8*B_*D_];       // ctx K-split partials
__device__ __align__(16) float  g_h4 [4*B_*4*D_];     // ffn1 K-split partials
__device__ __align__(16) float  g_o8 [8*B_*D_];       // ffn2 K-split partials

// ---- packed f32x2 helpers -------------------------------------------------
__device__ __forceinline__ void fma2(u64 &acc, u64 a, u64 b) {
    asm("fma.rn.f32x2 %0, %1, %2, %0;" : "+l"(acc) : "l"(a), "l"(b));
}
__device__ __forceinline__ u64 pack2(float v) {
    u64 r; asm("mov.b64 %0, {%1, %1};" : "=l"(r) : "f"(v)); return r;
}
__device__ __forceinline__ u64 pack2b(float a, float b) {
    u64 r; asm("mov.b64 %0, {%1, %2};" : "=l"(r) : "f"(a), "f"(b)); return r;
}
__device__ __forceinline__ float2 unpack2(u64 v) {
    float2 r; asm("mov.b64 {%0, %1}, %2;" : "=f"(r.x), "=f"(r.y) : "l"(v)); return r;
}
__device__ __forceinline__ float wred(float s) {
    #pragma unroll
    for (int o = 16; o > 0; o >>= 1) s += __shfl_xor_sync(0xffffffffu, s, o);
    return s;
}

// ---- tf32 mma helpers -----------------------------------------------------
__device__ __forceinline__ uint32_t f2tf(float x) {
    uint32_t r; asm("cvt.rna.tf32.f32 %0, %1;" : "=r"(r) : "f"(x)); return r;
}
__device__ __forceinline__ void mma_tf32(float* c, uint32_t a0, uint32_t a1,
                                         uint32_t a2, uint32_t a3,
                                         uint32_t b0, uint32_t b1) {
    asm volatile(
        "mma.sync.aligned.m16n8k8.row.col.f32.tf32.tf32.f32 "
        "{%0,%1,%2,%3}, {%4,%5,%6,%7}, {%8,%9}, {%0,%1,%2,%3};"
        : "+f"(c[0]), "+f"(c[1]), "+f"(c[2]), "+f"(c[3])
        : "r"(a0), "r"(a1), "r"(a2), "r"(a3), "r"(b0), "r"(b1));
}

// ===========================================================================
// GEMM64: 256 threads, 64-j tile x all 16 b over NCHUNK*32 k. Double-buffered.
// ===========================================================================
#define GEMM64(WL4, XL, NCHUNK, KOFF)                                          \
    int tid = threadIdx.x, jj = tid >> 3, bp = tid & 7;                        \
    __shared__ u64  Ws[2][64][34];                                             \
    __shared__ float Xs[2][32][18];                                            \
    u64 accA = 0ull, accB = 0ull;                                              \
    const int r0 = tid >> 3, c0 = (tid * 4) & 31;                              \
    const int r1 = 32 + r0,  c1 = c0;                                          \
    const int xk = tid & 31, xb = tid >> 5;                                    \
    float4 w0, w1; float x0, x1;                                               \
    w0 = WL4(r0, (KOFF) + c0); w1 = WL4(r1, (KOFF) + c1);                      \
    x0 = XL(xb, (KOFF) + xk);  x1 = XL(xb + 8, (KOFF) + xk);                   \
    {                                                                          \
        ulonglong2* p0 = (ulonglong2*)&Ws[0][r0][c0];                          \
        p0[0] = make_ulonglong2(pack2(w0.x), pack2(w0.y));                     \
        p0[1] = make_ulonglong2(pack2(w0.z), pack2(w0.w));                     \
        ulonglong2* p1 = (ulonglong2*)&Ws[0][r1][c1];                          \
        p1[0] = make_ulonglong2(pack2(w1.x), pack2(w1.y));                     \
        p1[1] = make_ulonglong2(pack2(w1.z), pack2(w1.w));                     \
        Xs[0][xk][xb] = x0; Xs[0][xk][xb + 8] = x1;                            \
    }                                                                          \
    __syncthreads();                                                           \
    for (int ch = 0; ch < (NCHUNK); ch++) {                                    \
        int cur = ch & 1;                                                      \
        if (ch + 1 < (NCHUNK)) {                                               \
            int kb = (KOFF) + (ch + 1) * 32;                                   \
            w0 = WL4(r0, kb + c0); w1 = WL4(r1, kb + c1);                      \
            x0 = XL(xb, kb + xk);  x1 = XL(xb + 8, kb + xk);                   \
        }                                                                      \
        _Pragma("unroll")                                                      \
        for (int k = 0; k < 32; k++) {                                         \
            u64 xv = *(const u64*)&Xs[cur][k][bp * 2];                         \
            fma2(accA, Ws[cur][jj][k],      xv);                               \
            fma2(accB, Ws[cur][32 + jj][k], xv);                               \
        }                                                                      \
        if (ch + 1 < (NCHUNK)) {                                               \
            int nxt = cur ^ 1;                                                 \
            ulonglong2* p0 = (ulonglong2*)&Ws[nxt][r0][c0];                    \
            p0[0] = make_ulonglong2(pack2(w0.x), pack2(w0.y));                 \
            p0[1] = make_ulonglong2(pack2(w0.z), pack2(w0.w));                 \
            ulonglong2* p1 = (ulonglong2*)&Ws[nxt][r1][c1];                    \
            p1[0] = make_ulonglong2(pack2(w1.x), pack2(w1.y));                 \
            p1[1] = make_ulonglong2(pack2(w1.z), pack2(w1.w));                 \
            Xs[nxt][xk][xb] = x0; Xs[nxt][xk][xb + 8] = x1;                    \
        }                                                                      \
        __syncthreads();                                                       \
    }                                                                          \
    float2 vA = unpack2(accA), vB = unpack2(accB);

// ---------------------------------------------------------------------------
// K1: qproj partials.  grid (16 jb, 8 ks), 256 thr
__global__ __launch_bounds__(256) void k_qproj(const float* __restrict__ dec_h,
                                               const float* __restrict__ Wq) {
    int j0 = blockIdx.x * 64, ks = blockIdx.y;
#define WL4(r, k) (*(const float4*)&Wq[(size_t)(j0 + (r)) * D_ + (k)])
#define XLD(b, k) dec_h[(size_t)(b) * D_ + (k)]
    GEMM64(WL4, XLD, 4, ks * 128)
#undef WL4
#undef XLD
    float* o = g_qp + (size_t)ks * (B_ * D_);
    o[(size_t)(2 * bp)     * D_ + j0 + jj]      = vA.x;
    o[(size_t)(2 * bp + 1) * D_ + j0 + jj]      = vA.y;
    o[(size_t)(2 * bp)     * D_ + j0 + 32 + jj] = vB.x;
    o[(size_t)(2 * bp + 1) * D_ + j0 + 32 + jj] = vB.y;
}

// ---------------------------------------------------------------------------
// K2: qt[b][d][h] = SCALE * Wk_h^T q_h (sums 8 qproj partials)
// grid 128 (h*8 + eighth), 128 thr
__global__ __launch_bounds__(128) void k_qtilde(const float* __restrict__ Wk) {
    int h = blockIdx.x >> 3, d0 = (blockIdx.x & 7) * 128, tid = threadIdx.x;
    __shared__ u64 qs2[64 * 8];          // [j][bpair]
    #pragma unroll
    for (int i = 0; i < 4; i++) {
        int idx = i * 128 + tid; int j = idx >> 3, bpp = idx & 7;
        float a = 0.f, bb = 0.f;
        #pragma unroll
        for (int ks = 0; ks < 8; ks++) {
            a  += g_qp[(size_t)ks * (B_ * D_) + (2 * bpp)     * D_ + h * HD_ + j];
            bb += g_qp[(size_t)ks * (B_ * D_) + (2 * bpp + 1) * D_ + h * HD_ + j];
        }
        qs2[j * 8 + bpp] = pack2b(a, bb);
    }
    __syncthreads();
    u64 acc[8];
    #pragma unroll
    for (int bp = 0; bp < 8; bp++) acc[bp] = 0ull;
    #pragma unroll 4
    for (int j = 0; j < HD_; j++) {
        u64 w2 = pack2(Wk[(size_t)(h * HD_ + j) * D_ + d0 + tid]);
        #pragma unroll
        for (int bp = 0; bp < 8; bp++) fma2(acc[bp], w2, qs2[j * 8 + bp]);
    }
    #pragma unroll
    for (int bp = 0; bp < 8; bp++) {
        float2 v = unpack2(acc[bp]);
        g_qt[(size_t)(2 * bp)     * D_ * NH_ + (d0 + tid) * NH_ + h] = 0.125f * v.x;
        g_qt[(size_t)(2 * bp + 1) * D_ * NH_ + (d0 + tid) * NH_ + h] = 0.125f * v.y;
    }
}

// ---------------------------------------------------------------------------
// K3: scores via tf32 mma.  grid (16 b, 32 t-tiles of 128), 256 thr (8 warps).
// Warp w owns m16-tile rows t0+16w..+15; N=16 heads = 2 n8-tiles; K=1024 in
// 32 double-buffered chunks of 32 (4 k8-steps each). Inputs cvt to tf32 at
// staging. Fragment layouts per PTX ISA m16n8k8.
__global__ __launch_bounds__(256) void k_scores(const float* __restrict__ enc) {
    const int b = blockIdx.x, t0 = blockIdx.y * 128;
    const int tid = threadIdx.x, w = tid >> 5, lane = tid & 31;
    __shared__ uint32_t es[2][128][36];   // enc tile (tf32 bits), pad 36
    __shared__ uint32_t qs[2][16][36];    // qt tile [h][k] (tf32 bits), pad 36
    const float* encb = enc + ((size_t)b * T_ + t0) * D_;
    const float* qtb  = g_qt + (size_t)b * D_ * NH_;

    float c0[4] = {0.f, 0.f, 0.f, 0.f};
    float c1[4] = {0.f, 0.f, 0.f, 0.f};

    // staging indices
    const int er = tid >> 1, ec4 = (tid & 1) * 4;      // enc: 2 float4 cols/thread? no:
    // enc tile: 128 rows x 32 k = 128 x 8 float4 = 1024 float4; 256 thr -> 4 each
    // idx = i*256+tid: row = idx>>3, c4 = idx&7
    (void)er; (void)ec4;

    float4 pe[4]; float pq[2];
    #pragma unroll
    for (int i = 0; i < 4; i++) {
        int idx = i * 256 + tid; int row = idx >> 3, c4 = idx & 7;
        pe[i] = *(const float4*)&encb[(size_t)row * D_ + c4 * 4];
    }
    #pragma unroll
    for (int i = 0; i < 2; i++) {
        int idx = i * 256 + tid; int h = idx & 15, k = idx >> 4;
        pq[i] = qtb[(size_t)k * NH_ + h];
    }
    #pragma unroll
    for (int i = 0; i < 4; i++) {
        int idx = i * 256 + tid; int row = idx >> 3, c4 = idx & 7;
        uint4 t4 = make_uint4(f2tf(pe[i].x), f2tf(pe[i].y),
                              f2tf(pe[i].z), f2tf(pe[i].w));
        *(uint4*)&es[0][row][c4 * 4] = t4;
    }
    #pragma unroll
    for (int i = 0; i < 2; i++) {
        int idx = i * 256 + tid; int h = idx & 15, k = idx >> 4;
        qs[0][h][k] = f2tf(pq[i]);
    }
    __syncthreads();

    const int arow = lane >> 2, acol = lane & 3;   // frag coords
    const int rbase = w * 16;

    for (int ch = 0; ch < 32; ch++) {
        int cur = ch & 1;
        if (ch + 1 < 32) {
            int k0 = (ch + 1) * 32;
            #pragma unroll
            for (int i = 0; i < 4; i++) {
                int idx = i * 256 + tid; int row = idx >> 3, c4 = idx & 7;
                pe[i] = *(const float4*)&encb[(size_t)row * D_ + k0 + c4 * 4];
            }
            #pragma unroll
            for (int i = 0; i < 2; i++) {
                int idx = i * 256 + tid; int h = idx & 15, k = idx >> 4;
                pq[i] = qtb[(size_t)(k0 + k) * NH_ + h];
            }
        }
        #pragma unroll
        for (int ks = 0; ks < 4; ks++) {
            int kk = ks * 8;
            uint32_t a0 = es[cur][rbase + arow    ][kk + acol];
            uint32_t a1 = es[cur][rbase + arow + 8][kk + acol];
            uint32_t a2 = es[cur][rbase + arow    ][kk + acol + 4];
            uint32_t a3 = es[cur][rbase + arow + 8][kk + acol + 4];
            uint32_t b0 = qs[cur][arow    ][kk + acol];       // n-tile 0: h=arow
            uint32_t b1 = qs[cur][arow    ][kk + acol + 4];
            mma_tf32(c0, a0, a1, a2, a3, b0, b1);
            uint32_t b2 = qs[cur][8 + arow][kk + acol];       // n-tile 1
            uint32_t b3 = qs[cur][8 + arow][kk + acol + 4];
            mma_tf32(c1, a0, a1, a2, a3, b2, b3);
        }
        if (ch + 1 < 32) {
            int nxt = cur ^ 1;
            #pragma unroll
            for (int i = 0; i < 4; i++) {
                int idx = i * 256 + tid; int row = idx >> 3, c4 = idx & 7;
                uint4 t4 = make_uint4(f2tf(pe[i].x), f2tf(pe[i].y),
                                      f2tf(pe[i].z), f2tf(pe[i].w));
                *(uint4*)&es[nxt][row][c4 * 4] = t4;
            }
            #pragma unroll
            for (int i = 0; i < 2; i++) {
                int idx = i * 256 + tid; int h = idx & 15, k = idx >> 4;
                qs[nxt][h][k] = f2tf(pq[i]);
            }
        }
        __syncthreads();
    }

    // store: D frag: c[0]=(arow, 2*acol), c[1]=(arow, 2*acol+1),
    //                c[2]=(arow+8, 2*acol), c[3]=(arow+8, 2*acol+1)
    int t = t0 + rbase + arow;
    int h0 = 2 * acol;                 // n-tile 0
    g_sc[((size_t)b * NH_ + h0    ) * T_ + t]     = c0[0];
    g_sc[((size_t)b * NH_ + h0 + 1) * T_ + t]     = c0[1];
    g_sc[((size_t)b * NH_ + h0    ) * T_ + t + 8] = c0[2];
    g_sc[((size_t)b * NH_ + h0 + 1) * T_ + t + 8] = c0[3];
    int h1 = 8 + 2 * acol;             // n-tile 1
    g_sc[((size_t)b * NH_ + h1    ) * T_ + t]     = c1[0];
    g_sc[((size_t)b * NH_ + h1 + 1) * T_ + t]     = c1[1];
    g_sc[((size_t)b * NH_ + h1    ) * T_ + t + 8] = c1[2];
    g_sc[((size_t)b * NH_ + h1 + 1) * T_ + t + 8] = c1[3];
}

// ---------------------------------------------------------------------------
// K4: softmax STATS only: g_ms[bh] = (max, 1/sumexp).  grid 256, 256 thr.
__global__ __launch_bounds__(256) void k_stats() {
    int bh = blockIdx.x, tid = threadIdx.x;
    const float4* sc4 = (const float4*)(g_sc + (size_t)bh * T_);
    __shared__ float red[8];
    __shared__ float sbc;

    float4 v[4];
    float m = -1e30f;
    #pragma unroll
    for (int k = 0; k < 4; k++) {
        v[k] = sc4[(k << 8) + tid];
        m = fmaxf(m, fmaxf(fmaxf(v[k].x, v[k].y), fmaxf(v[k].z, v[k].w)));
    }
    #pragma unroll
    for (int o = 16; o > 0; o >>= 1) m = fmaxf(m, __shfl_xor_sync(0xffffffffu, m, o));
    if ((tid & 31) == 0) red[tid >> 5] = m;
    __syncthreads();
    if (tid == 0) {
        float mm = red[0];
        #pragma unroll
        for (int i = 1; i < 8; i++) mm = fmaxf(mm, red[i]);
        sbc = mm;
    }
    __syncthreads();
    m = sbc;
    float s = 0.f;
    #pragma unroll
    for (int k = 0; k < 4; k++) {
        s += (__expf(v[k].x - m) + __expf(v[k].y - m)) +
             (__expf(v[k].z - m) + __expf(v[k].w - m));
    }
    s = wred(s);
    __syncthreads();
    if ((tid & 31) == 0) red[tid >> 5] = s;
    __syncthreads();
    if (tid == 0) {
        float ss = 0.f;
        #pragma unroll
        for (int i = 0; i < 8; i++) ss += red[i];
        g_ms[bh] = make_float2(m, 1.f / ss);
    }
}

// ---------------------------------------------------------------------------
// K5: wsum partials; normalize folded into staging.  grid (16,32), 256 thr
__global__ __launch_bounds__(256) void k_wsum(const float* __restrict__ enc) {
    int b = blockIdx.x, c = blockIdx.y, tid = threadIdx.x;
    __shared__ float w_s[TCH_][18];
    #pragma unroll
    for (int i = 0; i < 8; i++) {
        int idx = (i << 8) + tid;
        int h = idx >> 7, t = idx & 127;
        float2 ms = g_ms[b * NH_ + h];
        float sc = g_sc[((size_t)b * NH_ + h) * T_ + c * TCH_ + t];
        w_s[t][h] = __expf(sc - ms.x) * ms.y;
    }
    __syncthreads();

    u64 u[4][8];
    #pragma unroll
    for (int d = 0; d < 4; d++)
        #pragma unroll
        for (int hp = 0; hp < 8; hp++) u[d][hp] = 0ull;

    const float4* e4 = (const float4*)(enc + ((size_t)b * T_ + (size_t)c * TCH_) * D_) + tid;
    #pragma unroll 8
    for (int t = 0; t < TCH_; t++) {
        float4 ev = e4[(size_t)t * (D_ / 4)];
        const u64* wp = (const u64*)&w_s[t][0];
        u64 e0 = pack2(ev.x), e1 = pack2(ev.y), e2 = pack2(ev.z), e3 = pack2(ev.w);
        #pragma unroll
        for (int hp = 0; hp < 8; hp++) {
            u64 w2 = wp[hp];
            fma2(u[0][hp], e0, w2);
            fma2(u[1][hp], e1, w2);
            fma2(u[2][hp], e2, w2);
            fma2(u[3][hp], e3, w2);
        }
    }
    #pragma unroll
    for (int hp = 0; hp < 8; hp++) {
        float2 a0 = unpack2(u[0][hp]), a1 = unpack2(u[1][hp]),
               a2 = unpack2(u[2][hp]), a3 = unpack2(u[3][hp]);
        float4 lo = make_float4(a0.x, a1.x, a2.x, a3.x);
        float4 hi = make_float4(a0.y, a1.y, a2.y, a3.y);
        size_t base = (((size_t)c * B_ + b) * NH_) * D_ + 4 * tid;
        *(float4*)(g_up + base + (size_t)(2 * hp)     * D_) = lo;
        *(float4*)(g_up + base + (size_t)(2 * hp + 1) * D_) = hi;
    }
}

// ---------------------------------------------------------------------------
// K6: u = sum_c u_part   (wide streaming reduction, 1024 CTAs)
__global__ __launch_bounds__(256) void k_combine() {
    int idx = blockIdx.x * 256 + threadIdx.x;
    float s = 0.f;
    #pragma unroll
    for (int c = 0; c < NC_; c++) s += g_up[(size_t)c * (B_ * NH_ * D_) + idx];
    g_u[idx] = s;
}

// ---------------------------------------------------------------------------
// K7: ctx partials = Wv . u     grid (16 jb, 8 ks)
__global__ __launch_bounds__(256) void k_ctx(const float* __restrict__ Wv) {
    int j0 = blockIdx.x * 64, ks = blockIdx.y;
    int h  = blockIdx.x;
#define WL4(r, k) (*(const float4*)&Wv[(size_t)(j0 + (r)) * D_ + (k)])
#define XLD(b, k) g_u[((size_t)(b) * NH_ + h) * D_ + (k)]
    GEMM64(WL4, XLD, 4, ks * 128)
#undef WL4
#undef XLD
    float* o = g_cp + (size_t)ks * (B_ * D_);
    o[(size_t)(2 * bp)     * D_ + j0 + jj]      = vA.x;
    o[(size_t)(2 * bp + 1) * D_ + j0 + jj]      = vA.y;
    o[(size_t)(2 * bp)     * D_ + j0 + 32 + jj] = vB.x;
    o[(size_t)(2 * bp + 1) * D_ + j0 + 32 + jj] = vB.y;
}

// ---------------------------------------------------------------------------
// K8: ffn1 partials = cat(dec_h, sum_8 ctx_p) @ W1^T   grid (64 jb, 4 ks)
__global__ __launch_bounds__(256) void k_ffn1(const float* __restrict__ dec_h,
                                              const float* __restrict__ W1) {
    int j0 = blockIdx.x * 64, ks = blockIdx.y;
#define WL4(r, k) (*(const float4*)&W1[(size_t)(j0 + (r)) * (2 * D_) + (k)])
#define XLD(b, k) ((k) < D_ ? dec_h[(size_t)(b) * D_ + (k)]                    \
    : (((g_cp[(size_t)(b) * D_ + (k) - D_] +                                   \
         g_cp[(size_t)(B_ * D_) + (b) * D_ + (k) - D_]) +                      \
        (g_cp[(size_t)(2 * B_ * D_) + (b) * D_ + (k) - D_] +                   \
         g_cp[(size_t)(3 * B_ * D_) + (b) * D_ + (k) - D_])) +                 \
       ((g_cp[(size_t)(4 * B_ * D_) + (b) * D_ + (k) - D_] +                   \
         g_cp[(size_t)(5 * B_ * D_) + (b) * D_ + (k) - D_]) +                  \
        (g_cp[(size_t)(6 * B_ * D_) + (b) * D_ + (k) - D_] +                   \
         g_cp[(size_t)(7 * B_ * D_) + (b) * D_ + (k) - D_]))))
    GEMM64(WL4, XLD, 16, ks * 512)
#undef WL4
#undef XLD
    float* o = g_h4 + (size_t)ks * (B_ * 4 * D_);
    o[(size_t)(2 * bp)     * (4 * D_) + j0 + jj]      = vA.x;
    o[(size_t)(2 * bp + 1) * (4 * D_) + j0 + jj]      = vA.y;
    o[(size_t)(2 * bp)     * (4 * D_) + j0 + 32 + jj] = vB.x;
    o[(size_t)(2 * bp + 1) * (4 * D_) + j0 + 32 + jj] = vB.y;
}

// ---------------------------------------------------------------------------
// K9: ffn2 partials = silu(sum_4 h_p) @ W2^T   grid (16 jb, 8 ks)
__global__ __launch_bounds__(256) void k_ffn2(const float* __restrict__ W2) {
    int j0 = blockIdx.x * 64, ks = blockIdx.y;
#define WL4(r, k) (*(const float4*)&W2[(size_t)(j0 + (r)) * (4 * D_) + (k)])
#define XLD(b, k) ({                                                           \
        float _x = (g_h4[(size_t)(b) * (4 * D_) + (k)] +                       \
                    g_h4[(size_t)(B_ * 4 * D_) + (b) * (4 * D_) + (k)]) +      \
                   (g_h4[(size_t)(2 * B_ * 4 * D_) + (b) * (4 * D_) + (k)] +   \
                    g_h4[(size_t)(3 * B_ * 4 * D_) + (b) * (4 * D_) + (k)]);   \
        _x / (1.f + __expf(-_x)); })
    GEMM64(WL4, XLD, 16, ks * 512)
#undef WL4
#undef XLD
    float* o = g_o8 + (size_t)ks * (B_ * D_);
    o[(size_t)(2 * bp)     * D_ + j0 + jj]      = vA.x;
    o[(size_t)(2 * bp + 1) * D_ + j0 + jj]      = vA.y;
    o[(size_t)(2 * bp)     * D_ + j0 + 32 + jj] = vB.x;
    o[(size_t)(2 * bp + 1) * D_ + j0 + 32 + jj] = vB.y;
}

// ---------------------------------------------------------------------------
// K10: out = sum of 8 ffn2 partials   grid 16, 256 thr, float4
__global__ __launch_bounds__(256) void k_fin(float* __restrict__ outp) {
    int i = (blockIdx.x * 256 + threadIdx.x) * 4;
    float4 s = *(const float4*)&g_o8[i];
    #pragma unroll
    for (int ks = 1; ks < 8; ks++) {
        float4 p = *(const float4*)&g_o8[(size_t)ks * (B_ * D_) + i];
        s.x += p.x; s.y += p.y; s.z += p.z; s.w += p.w;
    }
    *(float4*)&outp[i] = s;
}

// ---------------------------------------------------------------------------
extern "C" void kernel_launch(void* const* d_in, const int* in_sizes, int n_in,
                              void* d_out, int out_size) {
    const float* dec_h = (const float*)d_in[0];
    const float* enc   = (const float*)d_in[1];
    const float* Wq    = (const float*)d_in[2];
    const float* Wk    = (const float*)d_in[3];
    const float* Wv    = (const float*)d_in[4];
    const float* W1    = (const float*)d_in[5];
    const float* W2    = (const float*)d_in[6];
    float* outp = (float*)d_out;

    k_qproj  <<<dim3(16, 8), 256>>>(dec_h, Wq);
    k_qtilde <<<128, 128>>>(Wk);
    k_scores <<<dim3(16, 32), 256>>>(enc);
    k_stats  <<<256, 256>>>();
    k_wsum   <<<dim3(16, 32), 256>>>(enc);
    k_combine<<<1024, 256>>>();
    k_ctx    <<<dim3(16, 8), 256>>>(Wv);
    k_ffn1   <<<dim3(64, 4), 256>>>(dec_h, W1);
    k_ffn2   <<<dim3(16, 8), 256>>>(W2);
    k_fin    <<<16, 256>>>(outp);
}